// round 8
// baseline (speedup 1.0000x reference)
#include <cuda_runtime.h>
#include <math.h>

#define NSAMP 64000
#define TILE  64
#define NTHR  512
#define SPB   8000

__device__ __align__(16) float g_Wt0[8 * 192 * 192];
__device__ __align__(16) float g_bc0[8 * 192];
__device__ __align__(16) float g_Wt1[8 * 128 * 256];
__device__ __align__(16) float g_Wt2[8 * 64 * 128];
__device__ float g_tmp[576 * NSAMP];

// ---- paired fp32 helpers (plain FFMA; no exotic instructions) ----
__device__ __forceinline__ void pfma(float2& a, float w, float2 x) {
    a.x = fmaf(w, x.x, a.x);
    a.y = fmaf(w, x.y, a.y);
}

__global__ void prep_weights_kernel(
    const float* __restrict__ coef,
    const float* __restrict__ w0, const float* __restrict__ b0,
    const float* __restrict__ ws0, const float* __restrict__ bs0,
    const float* __restrict__ w1, const float* __restrict__ ws1,
    const float* __restrict__ w2, const float* __restrict__ ws2)
{
    int idx = blockIdx.x * blockDim.x + threadIdx.x;
    const int S0 = 8 * 192 * 192;
    const int S1 = 8 * 192;
    const int S2 = 8 * 128 * 256;
    const int S3 = 8 * 64 * 128;
    if (idx < S0) {
        int b = idx / 36864, r = idx % 36864;
        int i = r / 192, o = r % 192;
        float v = ws0[o * 192 + i];
        #pragma unroll
        for (int e = 0; e < 8; e++)
            v = fmaf(coef[b * 8 + e], w0[e * 36864 + o * 192 + i], v);
        g_Wt0[b * 36864 + i * 192 + o] = v;
        return;
    }
    idx -= S0;
    if (idx < S1) {
        int b = idx / 192, o = idx % 192;
        float v = bs0[o];
        #pragma unroll
        for (int e = 0; e < 8; e++)
            v = fmaf(coef[b * 8 + e], b0[e * 192 + o], v);
        g_bc0[b * 192 + o] = v;
        return;
    }
    idx -= S1;
    if (idx < S2) {
        int b = idx / 32768, r = idx % 32768;
        int i = r / 256, o = r % 256;
        float v = ws1[o * 128 + i];
        #pragma unroll
        for (int e = 0; e < 8; e++)
            v = fmaf(coef[b * 8 + e], w1[e * 32768 + o * 128 + i], v);
        g_Wt1[b * 32768 + i * 256 + o] = v;
        return;
    }
    idx -= S2;
    if (idx < S3) {
        int b = idx / 8192, r = idx % 8192;
        int i = r / 128, o = r % 128;
        float v = ws2[o * 64 + i];
        #pragma unroll
        for (int e = 0; e < 8; e++)
            v = fmaf(coef[b * 8 + e], w2[e * 8192 + o * 64 + i], v);
        g_Wt2[b * 8192 + i * 128 + o] = v;
    }
}

__device__ __forceinline__ void mm3(const float* P, const float* Q, float* R) {
    #pragma unroll
    for (int i = 0; i < 3; i++)
        #pragma unroll
        for (int j = 0; j < 3; j++) {
            float acc = 0.f;
            #pragma unroll
            for (int k = 0; k < 3; k++) acc = fmaf(P[i * 3 + k], Q[k * 3 + j], acc);
            R[i * 3 + j] = acc;
        }
}
__device__ __forceinline__ void mm5(const float* P, const float* Q, float* R) {
    #pragma unroll
    for (int i = 0; i < 5; i++)
        #pragma unroll
        for (int j = 0; j < 5; j++) {
            float acc = 0.f;
            #pragma unroll
            for (int k = 0; k < 5; k++) acc = fmaf(P[i * 5 + k], Q[k * 5 + j], acc);
            R[i * 5 + j] = acc;
        }
}

__device__ void build_D(float a1, float a2, float a3,
                        const float* __restrict__ J1g,
                        const float* __restrict__ J2g,
                        float* __restrict__ D1, float* __restrict__ D2)
{
    float J1[9], J2[25];
    #pragma unroll
    for (int i = 0; i < 9; i++) J1[i] = J1g[i];
    #pragma unroll
    for (int i = 0; i < 25; i++) J2[i] = J2g[i];

    float X[3][9], Y[3][25];
    float aa[3] = {a1, a2, a3};
    #pragma unroll
    for (int t = 0; t < 3; t++) {
        float c1, s1, c2, s2;
        sincosf(aa[t], &s1, &c1);
        sincosf(2.0f * aa[t], &s2, &c2);
        float* Xp = X[t];
        Xp[0] = c1;  Xp[1] = 0.f; Xp[2] = s1;
        Xp[3] = 0.f; Xp[4] = 1.f; Xp[5] = 0.f;
        Xp[6] = -s1; Xp[7] = 0.f; Xp[8] = c1;
        float* Yp = Y[t];
        #pragma unroll
        for (int q = 0; q < 25; q++) Yp[q] = 0.f;
        Yp[0]  = c2;  Yp[4]  = s2;
        Yp[6]  = c1;  Yp[8]  = s1;
        Yp[12] = 1.f;
        Yp[16] = -s1; Yp[18] = c1;
        Yp[20] = -s2; Yp[24] = c2;
    }
    float T1[9], T2[9];
    mm3(X[0], J1, T1);
    mm3(T1, X[1], T2);
    mm3(T2, J1, T1);
    mm3(T1, X[2], D1);
    float U1[25], U2[25];
    mm5(Y[0], J2, U1);
    mm5(U1, Y[1], U2);
    mm5(U2, J2, U1);
    mm5(U1, Y[2], D2);
}

// Kernel 1 SMEM (floats): A[576*64] plain [dim][s]; ST[16*577]; D1f/D2f
#define SM_A    0
#define SM_ST   (576 * 64)
#define SM_D1F  (SM_ST + 16 * 577)
#define SM_D2F  (SM_D1F + 64 * 9)
#define SM1_TOT (SM_D2F + 64 * 25)

// ---- warp tiles: lane = output channel (coalesced weight loads) ----

// m0: 64 outputs x 32 samples, K=192
__device__ __forceinline__ void m0_tile(const float* __restrict__ A, int b,
                                        int og, int sh, int lane, int n0)
{
    int o0 = og * 64;
    int s0 = sh * 32;
    const float* wp = g_Wt0 + b * 36864 + o0 + lane;
    float bv0 = g_bc0[b * 192 + o0 + lane];
    float bv1 = g_bc0[b * 192 + o0 + 32 + lane];
    float2 a0[16], a1[16];
    #pragma unroll
    for (int j = 0; j < 16; j++) {
        a0[j] = make_float2(bv0, bv0);
        a1[j] = make_float2(bv1, bv1);
    }
    #pragma unroll 2
    for (int k = 0; k < 192; k++) {
        float w0 = wp[k * 192];
        float w1 = wp[k * 192 + 32];
        const float4* xv = (const float4*)(A + k * 64 + s0);
        #pragma unroll
        for (int j = 0; j < 8; j++) {
            float4 xx = xv[j];
            float2 xa = make_float2(xx.x, xx.y);
            float2 xb = make_float2(xx.z, xx.w);
            pfma(a0[2 * j],     w0, xa);
            pfma(a0[2 * j + 1], w0, xb);
            pfma(a1[2 * j],     w1, xa);
            pfma(a1[2 * j + 1], w1, xb);
        }
    }
    #pragma unroll
    for (int h = 0; h < 2; h++) {
        int o = o0 + 32 * h + lane;
        int dim = (o < 64) ? o : (o < 128) ? (3 * o - 127) : (5 * o - 382);
        float* gp = g_tmp + (size_t)dim * NSAMP + n0 + s0;
        float2* ap = h ? a1 : a0;
        #pragma unroll
        for (int t = 0; t < 8; t++) {
            *reinterpret_cast<float4*>(gp + 4 * t) =
                make_float4(ap[2 * t].x, ap[2 * t].y, ap[2 * t + 1].x, ap[2 * t + 1].y);
        }
    }
}

// m1: 32 output-pairs (r,i in same lane) x 16 samples x 2 input cols, K=128
__device__ __forceinline__ void m1_tile(const float* __restrict__ A, int b,
                                        int og, int sg, int lane, int n0)
{
    int o0 = og * 32;
    int s0 = sg * 16;
    const float* wp = g_Wt1 + b * 32768 + o0 + lane;
    float2 yr0[8], yr1[8], yi0[8], yi1[8];
    #pragma unroll
    for (int j = 0; j < 8; j++) {
        yr0[j] = yr1[j] = yi0[j] = yi1[j] = make_float2(0.f, 0.f);
    }
    #pragma unroll 2
    for (int k = 0; k < 128; k++) {
        float wr = wp[k * 256];
        float wi = wp[k * 256 + 128];
        const float4* x0v = (const float4*)(A + (192 + k) * 64 + s0);
        const float4* x1v = (const float4*)(A + (320 + k) * 64 + s0);
        #pragma unroll
        for (int j = 0; j < 4; j++) {
            float4 x0 = x0v[j], x1 = x1v[j];
            float2 x0a = make_float2(x0.x, x0.y), x0b = make_float2(x0.z, x0.w);
            float2 x1a = make_float2(x1.x, x1.y), x1b = make_float2(x1.z, x1.w);
            pfma(yr0[2 * j],     wr, x0a);
            pfma(yr0[2 * j + 1], wr, x0b);
            pfma(yr1[2 * j],     wr, x1a);
            pfma(yr1[2 * j + 1], wr, x1b);
            pfma(yi0[2 * j],     wi, x0a);
            pfma(yi0[2 * j + 1], wi, x0b);
            pfma(yi1[2 * j],     wi, x1a);
            pfma(yi1[2 * j + 1], wi, x1b);
        }
    }
    int k = o0 + lane;
    int dm = (k < 64) ? (64 + 3 * k) : (256 + 5 * (k - 64) + 1);
    int dp = dm + 2;
    float* gm = g_tmp + (size_t)dm * NSAMP + n0 + s0;
    float* gp = g_tmp + (size_t)dp * NSAMP + n0 + s0;
    #pragma unroll
    for (int t = 0; t < 4; t++) {
        *reinterpret_cast<float4*>(gm + 4 * t) = make_float4(
            yr0[2 * t].x     - yi1[2 * t].x,
            yr0[2 * t].y     - yi1[2 * t].y,
            yr0[2 * t + 1].x - yi1[2 * t + 1].x,
            yr0[2 * t + 1].y - yi1[2 * t + 1].y);
        *reinterpret_cast<float4*>(gp + 4 * t) = make_float4(
            yr1[2 * t].x     + yi0[2 * t].x,
            yr1[2 * t].y     + yi0[2 * t].y,
            yr1[2 * t + 1].x + yi0[2 * t + 1].x,
            yr1[2 * t + 1].y + yi0[2 * t + 1].y);
    }
}

// m2: 32 output-pairs x 16 samples x 2 input cols, K=64
__device__ __forceinline__ void m2_tile(const float* __restrict__ A, int b,
                                        int og, int sg, int lane, int n0)
{
    int o0 = og * 32;
    int s0 = sg * 16;
    const float* wp = g_Wt2 + b * 8192 + o0 + lane;
    float2 yr0[8], yr1[8], yi0[8], yi1[8];
    #pragma unroll
    for (int j = 0; j < 8; j++) {
        yr0[j] = yr1[j] = yi0[j] = yi1[j] = make_float2(0.f, 0.f);
    }
    #pragma unroll 2
    for (int k = 0; k < 64; k++) {
        float wr = wp[k * 128];
        float wi = wp[k * 128 + 64];
        const float4* x0v = (const float4*)(A + (448 + k) * 64 + s0);
        const float4* x1v = (const float4*)(A + (512 + k) * 64 + s0);
        #pragma unroll
        for (int j = 0; j < 4; j++) {
            float4 x0 = x0v[j], x1 = x1v[j];
            float2 x0a = make_float2(x0.x, x0.y), x0b = make_float2(x0.z, x0.w);
            float2 x1a = make_float2(x1.x, x1.y), x1b = make_float2(x1.z, x1.w);
            pfma(yr0[2 * j],     wr, x0a);
            pfma(yr0[2 * j + 1], wr, x0b);
            pfma(yr1[2 * j],     wr, x1a);
            pfma(yr1[2 * j + 1], wr, x1b);
            pfma(yi0[2 * j],     wi, x0a);
            pfma(yi0[2 * j + 1], wi, x0b);
            pfma(yi1[2 * j],     wi, x1a);
            pfma(yi1[2 * j + 1], wi, x1b);
        }
    }
    int k = o0 + lane;
    int dm = 256 + 5 * k;
    int dp = dm + 4;
    float* gm = g_tmp + (size_t)dm * NSAMP + n0 + s0;
    float* gp = g_tmp + (size_t)dp * NSAMP + n0 + s0;
    #pragma unroll
    for (int t = 0; t < 4; t++) {
        *reinterpret_cast<float4*>(gm + 4 * t) = make_float4(
            yr0[2 * t].x     - yi1[2 * t].x,
            yr0[2 * t].y     - yi1[2 * t].y,
            yr0[2 * t + 1].x - yi1[2 * t + 1].x,
            yr0[2 * t + 1].y - yi1[2 * t + 1].y);
        *reinterpret_cast<float4*>(gp + 4 * t) = make_float4(
            yr1[2 * t].x     + yi0[2 * t].x,
            yr1[2 * t].y     + yi0[2 * t].y,
            yr1[2 * t + 1].x + yi0[2 * t + 1].x,
            yr1[2 * t + 1].y + yi0[2 * t + 1].y);
    }
}

__global__ __launch_bounds__(NTHR, 1)
void so2_gemm_kernel(const float* __restrict__ x,
                     const float* __restrict__ alpha,
                     const float* __restrict__ beta,
                     const float* __restrict__ gamma_,
                     const float* __restrict__ Jd1,
                     const float* __restrict__ Jd2)
{
    extern __shared__ float sm[];
    float* A   = sm + SM_A;
    float* ST  = sm + SM_ST;
    float* D1f = sm + SM_D1F;
    float* D2f = sm + SM_D2F;

    const int tid  = threadIdx.x;
    const int w    = tid >> 5;
    const int lane = tid & 31;
    const int n0   = blockIdx.x * TILE;
    const int b    = n0 / SPB;
    const float* xg = x + (size_t)n0 * 576;

    // ---- Phase 1: fwd Wigner (threads 0-63) + stage pass 0 ----
    if (tid < 64) {
        int n = n0 + tid;
        build_D(alpha[n], beta[n], gamma_[n], Jd1, Jd2,
                D1f + tid * 9, D2f + tid * 25);
    } else {
        for (int idx = tid - 64; idx < 16 * 576; idx += NTHR - 64) {
            int s = idx / 576, d = idx % 576;
            ST[s * 577 + d] = xg[idx];
        }
    }
    __syncthreads();

    // ---- 4 passes: gather+rotate 16 samples, then stage next 16 ----
    for (int p = 0; p < 4; p++) {
        {
            int s16 = tid & 15;
            int grp = tid >> 4;
            int s   = p * 16 + s16;
            const float* br = ST + s16 * 577;
            float d1[9], d2[25];
            #pragma unroll
            for (int j = 0; j < 9; j++)  d1[j] = D1f[s * 9 + j];
            #pragma unroll
            for (int j = 0; j < 25; j++) d2[j] = D2f[s * 25 + j];
            #pragma unroll
            for (int cc = 0; cc < 2; cc++) {
                int c = grp + 32 * cc;
                A[c * 64 + s] = br[c];
                float v0 = br[64 + 3 * c], v1 = br[64 + 3 * c + 1], v2 = br[64 + 3 * c + 2];
                A[(192 + c) * 64 + s] = fmaf(d1[0], v0, fmaf(d1[1], v1, d1[2] * v2));
                A[(64  + c) * 64 + s] = fmaf(d1[3], v0, fmaf(d1[4], v1, d1[5] * v2));
                A[(320 + c) * 64 + s] = fmaf(d1[6], v0, fmaf(d1[7], v1, d1[8] * v2));
                float u0 = br[256 + 5 * c],     u1 = br[256 + 5 * c + 1], u2 = br[256 + 5 * c + 2];
                float u3 = br[256 + 5 * c + 3], u4 = br[256 + 5 * c + 4];
                float rr[5];
                #pragma unroll
                for (int i = 0; i < 5; i++)
                    rr[i] = fmaf(d2[i*5+0], u0, fmaf(d2[i*5+1], u1, fmaf(d2[i*5+2], u2,
                            fmaf(d2[i*5+3], u3, d2[i*5+4] * u4))));
                A[(448 + c) * 64 + s] = rr[0];
                A[(256 + c) * 64 + s] = rr[1];
                A[(128 + c) * 64 + s] = rr[2];
                A[(384 + c) * 64 + s] = rr[3];
                A[(512 + c) * 64 + s] = rr[4];
            }
        }
        __syncthreads();
        if (p < 3) {
            const float* xp = xg + (p + 1) * 16 * 576;
            for (int idx = tid; idx < 16 * 576; idx += NTHR) {
                int s = idx / 576, d = idx % 576;
                ST[s * 577 + d] = xp[idx];
            }
            __syncthreads();
        }
    }

    // ---- Phase 2: register-tiled GEMMs, lane = output channel ----
    // warps 0-7:  m1, og=w>>1, sg=2*(w&1)+{0,1}
    // warps 8-13: m0 (og=t>>1, sh=t&1), then m2 (og=t>>2, sg=t&3), t=w-8
    // warps 14-15: m2 only (t=6,7)
    if (w < 8) {
        int og = w >> 1;
        int sgb = (w & 1) * 2;
        m1_tile(A, b, og, sgb,     lane, n0);
        m1_tile(A, b, og, sgb + 1, lane, n0);
    } else {
        int t = w - 8;
        if (t < 6) m0_tile(A, b, t >> 1, t & 1, lane, n0);
        m2_tile(A, b, t >> 2, t & 3, lane, n0);
    }
}

// Kernel 2: back-rotation.
#define K2THR 256
#define SM2_S   0
#define SM2_D1B (576 * 33)
#define SM2_D2B (SM2_D1B + 32 * 9)
#define SM2_TOT (SM2_D2B + 32 * 25)

__global__ __launch_bounds__(K2THR, 1)
void so2_backrot_kernel(const float* __restrict__ alpha,
                        const float* __restrict__ beta,
                        const float* __restrict__ gamma_,
                        const float* __restrict__ Jd1,
                        const float* __restrict__ Jd2,
                        float* __restrict__ out)
{
    extern __shared__ float sm[];
    float* S   = sm + SM2_S;
    float* D1b = sm + SM2_D1B;
    float* D2b = sm + SM2_D2B;

    const int tid  = threadIdx.x;
    const int w    = tid >> 5;
    const int lane = tid & 31;
    const int n0   = blockIdx.x * 32;

    for (int idx = tid; idx < 576 * 32; idx += K2THR) {
        int d = idx >> 5, s = idx & 31;
        S[d * 33 + s] = g_tmp[d * NSAMP + n0 + s];
    }
    if (tid < 32) {
        int n = n0 + tid;
        build_D(-gamma_[n], -beta[n], -alpha[n], Jd1, Jd2,
                D1b + tid * 9, D2b + tid * 25);
    }
    __syncthreads();

    {
        float e1[9], e2[25];
        #pragma unroll
        for (int j = 0; j < 9; j++)  e1[j] = D1b[lane * 9 + j];
        #pragma unroll
        for (int j = 0; j < 25; j++) e2[j] = D2b[lane * 25 + j];
        #pragma unroll
        for (int k = 0; k < 8; k++) {
            int c = w + 8 * k;
            float v0 = S[(64 + 3 * c) * 33 + lane];
            float v1 = S[(64 + 3 * c + 1) * 33 + lane];
            float v2 = S[(64 + 3 * c + 2) * 33 + lane];
            S[(64 + 3 * c) * 33 + lane]     = fmaf(e1[0], v0, fmaf(e1[1], v1, e1[2] * v2));
            S[(64 + 3 * c + 1) * 33 + lane] = fmaf(e1[3], v0, fmaf(e1[4], v1, e1[5] * v2));
            S[(64 + 3 * c + 2) * 33 + lane] = fmaf(e1[6], v0, fmaf(e1[7], v1, e1[8] * v2));
            float u0 = S[(256 + 5 * c) * 33 + lane];
            float u1 = S[(256 + 5 * c + 1) * 33 + lane];
            float u2 = S[(256 + 5 * c + 2) * 33 + lane];
            float u3 = S[(256 + 5 * c + 3) * 33 + lane];
            float u4 = S[(256 + 5 * c + 4) * 33 + lane];
            #pragma unroll
            for (int i = 0; i < 5; i++)
                S[(256 + 5 * c + i) * 33 + lane] =
                    fmaf(e2[i*5+0], u0, fmaf(e2[i*5+1], u1, fmaf(e2[i*5+2], u2,
                    fmaf(e2[i*5+3], u3, e2[i*5+4] * u4))));
        }
    }
    __syncthreads();

    for (int idx = tid; idx < 32 * 576; idx += K2THR) {
        int s = idx / 576, d = idx % 576;
        out[(size_t)(n0 + s) * 576 + d] = S[d * 33 + s];
    }
}

extern "C" void kernel_launch(void* const* d_in, const int* in_sizes, int n_in,
                              void* d_out, int out_size)
{
    const float* x     = (const float*)d_in[0];
    const float* alpha = (const float*)d_in[1];
    const float* beta  = (const float*)d_in[2];
    const float* gamma_= (const float*)d_in[3];
    const float* coef  = (const float*)d_in[4];
    const float* Jd1   = (const float*)d_in[5];
    const float* Jd2   = (const float*)d_in[6];
    const float* w0    = (const float*)d_in[7];
    const float* b0    = (const float*)d_in[8];
    const float* ws0   = (const float*)d_in[9];
    const float* bs0   = (const float*)d_in[10];
    const float* w1    = (const float*)d_in[11];
    const float* ws1   = (const float*)d_in[12];
    const float* w2    = (const float*)d_in[13];
    const float* ws2   = (const float*)d_in[14];
    float* out = (float*)d_out;

    const int totalW = 8 * 192 * 192 + 8 * 192 + 8 * 128 * 256 + 8 * 64 * 128;
    prep_weights_kernel<<<(totalW + 255) / 256, 256>>>(coef, w0, b0, ws0, bs0,
                                                       w1, ws1, w2, ws2);

    const int smem1 = SM1_TOT * sizeof(float);
    cudaFuncSetAttribute(so2_gemm_kernel,
                         cudaFuncAttributeMaxDynamicSharedMemorySize, smem1);
    so2_gemm_kernel<<<NSAMP / TILE, NTHR, smem1>>>(x, alpha, beta, gamma_, Jd1, Jd2);

    const int smem2 = SM2_TOT * sizeof(float);
    cudaFuncSetAttribute(so2_backrot_kernel,
                         cudaFuncAttributeMaxDynamicSharedMemorySize, smem2);
    so2_backrot_kernel<<<NSAMP / 32, K2THR, smem2>>>(alpha, beta, gamma_,
                                                     Jd1, Jd2, out);
}

// round 9
// speedup vs baseline: 1.3249x; 1.3249x over previous
#include <cuda_runtime.h>
#include <math.h>

#define NSAMP 64000
#define TILE  64
#define NTHR  512
#define SPB   8000

__device__ __align__(16) float g_Wt0[8 * 192 * 192];
__device__ __align__(16) float g_bc0[8 * 192];
__device__ __align__(16) float g_Wt1[8 * 128 * 256];
__device__ __align__(16) float g_Wt2[8 * 64 * 128];
__device__ float g_tmp[576 * NSAMP];

__device__ __forceinline__ void pfma(float2& a, float w, float2 x) {
    a.x = fmaf(w, x.x, a.x);
    a.y = fmaf(w, x.y, a.y);
}

__global__ void prep_weights_kernel(
    const float* __restrict__ coef,
    const float* __restrict__ w0, const float* __restrict__ b0,
    const float* __restrict__ ws0, const float* __restrict__ bs0,
    const float* __restrict__ w1, const float* __restrict__ ws1,
    const float* __restrict__ w2, const float* __restrict__ ws2)
{
    int idx = blockIdx.x * blockDim.x + threadIdx.x;
    const int S0 = 8 * 192 * 192;
    const int S1 = 8 * 192;
    const int S2 = 8 * 128 * 256;
    const int S3 = 8 * 64 * 128;
    if (idx < S0) {
        int b = idx / 36864, r = idx % 36864;
        int i = r / 192, o = r % 192;
        float v = ws0[o * 192 + i];
        #pragma unroll
        for (int e = 0; e < 8; e++)
            v = fmaf(coef[b * 8 + e], w0[e * 36864 + o * 192 + i], v);
        g_Wt0[b * 36864 + i * 192 + o] = v;
        return;
    }
    idx -= S0;
    if (idx < S1) {
        int b = idx / 192, o = idx % 192;
        float v = bs0[o];
        #pragma unroll
        for (int e = 0; e < 8; e++)
            v = fmaf(coef[b * 8 + e], b0[e * 192 + o], v);
        g_bc0[b * 192 + o] = v;
        return;
    }
    idx -= S1;
    if (idx < S2) {
        int b = idx / 32768, r = idx % 32768;
        int i = r / 256, o = r % 256;
        float v = ws1[o * 128 + i];
        #pragma unroll
        for (int e = 0; e < 8; e++)
            v = fmaf(coef[b * 8 + e], w1[e * 32768 + o * 128 + i], v);
        g_Wt1[b * 32768 + i * 256 + o] = v;
        return;
    }
    idx -= S2;
    if (idx < S3) {
        int b = idx / 8192, r = idx % 8192;
        int i = r / 128, o = r % 128;
        float v = ws2[o * 64 + i];
        #pragma unroll
        for (int e = 0; e < 8; e++)
            v = fmaf(coef[b * 8 + e], w2[e * 8192 + o * 64 + i], v);
        g_Wt2[b * 8192 + i * 128 + o] = v;
    }
}

__device__ __forceinline__ void mm3(const float* P, const float* Q, float* R) {
    #pragma unroll
    for (int i = 0; i < 3; i++)
        #pragma unroll
        for (int j = 0; j < 3; j++) {
            float acc = 0.f;
            #pragma unroll
            for (int k = 0; k < 3; k++) acc = fmaf(P[i * 3 + k], Q[k * 3 + j], acc);
            R[i * 3 + j] = acc;
        }
}
__device__ __forceinline__ void mm5(const float* P, const float* Q, float* R) {
    #pragma unroll
    for (int i = 0; i < 5; i++)
        #pragma unroll
        for (int j = 0; j < 5; j++) {
            float acc = 0.f;
            #pragma unroll
            for (int k = 0; k < 5; k++) acc = fmaf(P[i * 5 + k], Q[k * 5 + j], acc);
            R[i * 5 + j] = acc;
        }
}

__device__ void build_D(float a1, float a2, float a3,
                        const float* __restrict__ J1g,
                        const float* __restrict__ J2g,
                        float* __restrict__ D1, float* __restrict__ D2)
{
    float J1[9], J2[25];
    #pragma unroll
    for (int i = 0; i < 9; i++) J1[i] = J1g[i];
    #pragma unroll
    for (int i = 0; i < 25; i++) J2[i] = J2g[i];

    float X[3][9], Y[3][25];
    float aa[3] = {a1, a2, a3};
    #pragma unroll
    for (int t = 0; t < 3; t++) {
        float c1, s1, c2, s2;
        sincosf(aa[t], &s1, &c1);
        sincosf(2.0f * aa[t], &s2, &c2);
        float* Xp = X[t];
        Xp[0] = c1;  Xp[1] = 0.f; Xp[2] = s1;
        Xp[3] = 0.f; Xp[4] = 1.f; Xp[5] = 0.f;
        Xp[6] = -s1; Xp[7] = 0.f; Xp[8] = c1;
        float* Yp = Y[t];
        #pragma unroll
        for (int q = 0; q < 25; q++) Yp[q] = 0.f;
        Yp[0]  = c2;  Yp[4]  = s2;
        Yp[6]  = c1;  Yp[8]  = s1;
        Yp[12] = 1.f;
        Yp[16] = -s1; Yp[18] = c1;
        Yp[20] = -s2; Yp[24] = c2;
    }
    float T1[9], T2[9];
    mm3(X[0], J1, T1);
    mm3(T1, X[1], T2);
    mm3(T2, J1, T1);
    mm3(T1, X[2], D1);
    float U1[25], U2[25];
    mm5(Y[0], J2, U1);
    mm5(U1, Y[1], U2);
    mm5(U2, J2, U1);
    mm5(U1, Y[2], D2);
}

// Kernel 1 SMEM (floats): A[576*64] plain [dim][s]; ST[16*577]; D1f/D2f
#define SM_A    0
#define SM_ST   (576 * 64)
#define SM_D1F  (SM_ST + 16 * 577)
#define SM_D2F  (SM_D1F + 64 * 9)
#define SM1_TOT (SM_D2F + 64 * 25)

// ---- warp tiles: lane = output channel, double-buffered weight prefetch ----

// m0: 64 outputs x 32 samples, K=192, k-chunks of 4
__device__ __forceinline__ void m0_tile(const float* __restrict__ A, int b,
                                        int og, int sh, int lane, int n0)
{
    int o0 = og * 64;
    int s0 = sh * 32;
    const float* wp = g_Wt0 + b * 36864 + o0 + lane;
    float bv0 = g_bc0[b * 192 + o0 + lane];
    float bv1 = g_bc0[b * 192 + o0 + 32 + lane];
    float2 a0[16], a1[16];
    #pragma unroll
    for (int j = 0; j < 16; j++) {
        a0[j] = make_float2(bv0, bv0);
        a1[j] = make_float2(bv1, bv1);
    }
    float w0b[2][4], w1b[2][4];
    #pragma unroll
    for (int j = 0; j < 4; j++) {
        w0b[0][j] = wp[j * 192];
        w1b[0][j] = wp[j * 192 + 32];
    }
    int cur = 0;
    #pragma unroll 1
    for (int k0 = 0; k0 < 192; k0 += 4) {
        int nxt = cur ^ 1;
        if (k0 + 4 < 192) {
            #pragma unroll
            for (int j = 0; j < 4; j++) {
                w0b[nxt][j] = wp[(k0 + 4 + j) * 192];
                w1b[nxt][j] = wp[(k0 + 4 + j) * 192 + 32];
            }
        }
        #pragma unroll
        for (int j = 0; j < 4; j++) {
            float w0 = w0b[cur][j];
            float w1 = w1b[cur][j];
            const float4* xv = (const float4*)(A + (k0 + j) * 64 + s0);
            #pragma unroll
            for (int q = 0; q < 8; q++) {
                float4 xx = xv[q];
                float2 xa = make_float2(xx.x, xx.y);
                float2 xb = make_float2(xx.z, xx.w);
                pfma(a0[2 * q],     w0, xa);
                pfma(a0[2 * q + 1], w0, xb);
                pfma(a1[2 * q],     w1, xa);
                pfma(a1[2 * q + 1], w1, xb);
            }
        }
        cur = nxt;
    }
    #pragma unroll
    for (int h = 0; h < 2; h++) {
        int o = o0 + 32 * h + lane;
        int dim = (o < 64) ? o : (o < 128) ? (3 * o - 127) : (5 * o - 382);
        float* gp = g_tmp + (size_t)dim * NSAMP + n0 + s0;
        float2* ap = h ? a1 : a0;
        #pragma unroll
        for (int t = 0; t < 8; t++) {
            *reinterpret_cast<float4*>(gp + 4 * t) =
                make_float4(ap[2 * t].x, ap[2 * t].y, ap[2 * t + 1].x, ap[2 * t + 1].y);
        }
    }
}

// m1: 32 output-pairs x 16 samples x 2 input cols, K=128, k-chunks of 4
__device__ __forceinline__ void m1_tile(const float* __restrict__ A, int b,
                                        int og, int sg, int lane, int n0)
{
    int o0 = og * 32;
    int s0 = sg * 16;
    const float* wp = g_Wt1 + b * 32768 + o0 + lane;
    float2 yr0[8], yr1[8], yi0[8], yi1[8];
    #pragma unroll
    for (int j = 0; j < 8; j++) {
        yr0[j] = yr1[j] = yi0[j] = yi1[j] = make_float2(0.f, 0.f);
    }
    float wrb[2][4], wib[2][4];
    #pragma unroll
    for (int j = 0; j < 4; j++) {
        wrb[0][j] = wp[j * 256];
        wib[0][j] = wp[j * 256 + 128];
    }
    int cur = 0;
    #pragma unroll 1
    for (int k0 = 0; k0 < 128; k0 += 4) {
        int nxt = cur ^ 1;
        if (k0 + 4 < 128) {
            #pragma unroll
            for (int j = 0; j < 4; j++) {
                wrb[nxt][j] = wp[(k0 + 4 + j) * 256];
                wib[nxt][j] = wp[(k0 + 4 + j) * 256 + 128];
            }
        }
        #pragma unroll
        for (int j = 0; j < 4; j++) {
            float wr = wrb[cur][j];
            float wi = wib[cur][j];
            const float4* x0v = (const float4*)(A + (192 + k0 + j) * 64 + s0);
            const float4* x1v = (const float4*)(A + (320 + k0 + j) * 64 + s0);
            #pragma unroll
            for (int q = 0; q < 4; q++) {
                float4 x0 = x0v[q], x1 = x1v[q];
                float2 x0a = make_float2(x0.x, x0.y), x0b = make_float2(x0.z, x0.w);
                float2 x1a = make_float2(x1.x, x1.y), x1b = make_float2(x1.z, x1.w);
                // q indexes 4 samples per float4; accumulate into slot q
                pfma(yr0[2 * q],     wr, x0a);
                pfma(yr0[2 * q + 1], wr, x0b);
                pfma(yr1[2 * q],     wr, x1a);
                pfma(yr1[2 * q + 1], wr, x1b);
                pfma(yi0[2 * q],     wi, x0a);
                pfma(yi0[2 * q + 1], wi, x0b);
                pfma(yi1[2 * q],     wi, x1a);
                pfma(yi1[2 * q + 1], wi, x1b);
            }
        }
        cur = nxt;
    }
    int k = o0 + lane;
    int dm = (k < 64) ? (64 + 3 * k) : (256 + 5 * (k - 64) + 1);
    int dp = dm + 2;
    float* gm = g_tmp + (size_t)dm * NSAMP + n0 + s0;
    float* gp = g_tmp + (size_t)dp * NSAMP + n0 + s0;
    #pragma unroll
    for (int t = 0; t < 4; t++) {
        *reinterpret_cast<float4*>(gm + 4 * t) = make_float4(
            yr0[2 * t].x     - yi1[2 * t].x,
            yr0[2 * t].y     - yi1[2 * t].y,
            yr0[2 * t + 1].x - yi1[2 * t + 1].x,
            yr0[2 * t + 1].y - yi1[2 * t + 1].y);
        *reinterpret_cast<float4*>(gp + 4 * t) = make_float4(
            yr1[2 * t].x     + yi0[2 * t].x,
            yr1[2 * t].y     + yi0[2 * t].y,
            yr1[2 * t + 1].x + yi0[2 * t + 1].x,
            yr1[2 * t + 1].y + yi0[2 * t + 1].y);
    }
}

// m2: 32 output-pairs x 16 samples x 2 input cols, K=64, k-chunks of 4
__device__ __forceinline__ void m2_tile(const float* __restrict__ A, int b,
                                        int og, int sg, int lane, int n0)
{
    int o0 = og * 32;
    int s0 = sg * 16;
    const float* wp = g_Wt2 + b * 8192 + o0 + lane;
    float2 yr0[8], yr1[8], yi0[8], yi1[8];
    #pragma unroll
    for (int j = 0; j < 8; j++) {
        yr0[j] = yr1[j] = yi0[j] = yi1[j] = make_float2(0.f, 0.f);
    }
    float wrb[2][4], wib[2][4];
    #pragma unroll
    for (int j = 0; j < 4; j++) {
        wrb[0][j] = wp[j * 128];
        wib[0][j] = wp[j * 128 + 64];
    }
    int cur = 0;
    #pragma unroll 1
    for (int k0 = 0; k0 < 64; k0 += 4) {
        int nxt = cur ^ 1;
        if (k0 + 4 < 64) {
            #pragma unroll
            for (int j = 0; j < 4; j++) {
                wrb[nxt][j] = wp[(k0 + 4 + j) * 128];
                wib[nxt][j] = wp[(k0 + 4 + j) * 128 + 64];
            }
        }
        #pragma unroll
        for (int j = 0; j < 4; j++) {
            float wr = wrb[cur][j];
            float wi = wib[cur][j];
            const float4* x0v = (const float4*)(A + (448 + k0 + j) * 64 + s0);
            const float4* x1v = (const float4*)(A + (512 + k0 + j) * 64 + s0);
            #pragma unroll
            for (int q = 0; q < 4; q++) {
                float4 x0 = x0v[q], x1 = x1v[q];
                float2 x0a = make_float2(x0.x, x0.y), x0b = make_float2(x0.z, x0.w);
                float2 x1a = make_float2(x1.x, x1.y), x1b = make_float2(x1.z, x1.w);
                pfma(yr0[2 * q],     wr, x0a);
                pfma(yr0[2 * q + 1], wr, x0b);
                pfma(yr1[2 * q],     wr, x1a);
                pfma(yr1[2 * q + 1], wr, x1b);
                pfma(yi0[2 * q],     wi, x0a);
                pfma(yi0[2 * q + 1], wi, x0b);
                pfma(yi1[2 * q],     wi, x1a);
                pfma(yi1[2 * q + 1], wi, x1b);
            }
        }
        cur = nxt;
    }
    int k = o0 + lane;
    int dm = 256 + 5 * k;
    int dp = dm + 4;
    float* gm = g_tmp + (size_t)dm * NSAMP + n0 + s0;
    float* gp = g_tmp + (size_t)dp * NSAMP + n0 + s0;
    #pragma unroll
    for (int t = 0; t < 4; t++) {
        *reinterpret_cast<float4*>(gm + 4 * t) = make_float4(
            yr0[2 * t].x     - yi1[2 * t].x,
            yr0[2 * t].y     - yi1[2 * t].y,
            yr0[2 * t + 1].x - yi1[2 * t + 1].x,
            yr0[2 * t + 1].y - yi1[2 * t + 1].y);
        *reinterpret_cast<float4*>(gp + 4 * t) = make_float4(
            yr1[2 * t].x     + yi0[2 * t].x,
            yr1[2 * t].y     + yi0[2 * t].y,
            yr1[2 * t + 1].x + yi0[2 * t + 1].x,
            yr1[2 * t + 1].y + yi0[2 * t + 1].y);
    }
}

__global__ __launch_bounds__(NTHR, 1)
void so2_gemm_kernel(const float* __restrict__ x,
                     const float* __restrict__ alpha,
                     const float* __restrict__ beta,
                     const float* __restrict__ gamma_,
                     const float* __restrict__ Jd1,
                     const float* __restrict__ Jd2)
{
    extern __shared__ float sm[];
    float* A   = sm + SM_A;
    float* ST  = sm + SM_ST;
    float* D1f = sm + SM_D1F;
    float* D2f = sm + SM_D2F;

    const int tid  = threadIdx.x;
    const int w    = tid >> 5;
    const int lane = tid & 31;
    const int n0   = blockIdx.x * TILE;
    const int b    = n0 / SPB;
    const float* xg = x + (size_t)n0 * 576;

    // ---- Phase 1: fwd Wigner (threads 0-63) + stage pass 0 ----
    if (tid < 64) {
        int n = n0 + tid;
        build_D(alpha[n], beta[n], gamma_[n], Jd1, Jd2,
                D1f + tid * 9, D2f + tid * 25);
    } else {
        for (int idx = tid - 64; idx < 16 * 576; idx += NTHR - 64) {
            int s = idx / 576, d = idx % 576;
            ST[s * 577 + d] = xg[idx];
        }
    }
    __syncthreads();

    // ---- 4 passes: gather+rotate 16 samples, then stage next 16 ----
    for (int p = 0; p < 4; p++) {
        {
            int s16 = tid & 15;
            int grp = tid >> 4;
            int s   = p * 16 + s16;
            const float* br = ST + s16 * 577;
            float d1[9], d2[25];
            #pragma unroll
            for (int j = 0; j < 9; j++)  d1[j] = D1f[s * 9 + j];
            #pragma unroll
            for (int j = 0; j < 25; j++) d2[j] = D2f[s * 25 + j];
            #pragma unroll
            for (int cc = 0; cc < 2; cc++) {
                int c = grp + 32 * cc;
                A[c * 64 + s] = br[c];
                float v0 = br[64 + 3 * c], v1 = br[64 + 3 * c + 1], v2 = br[64 + 3 * c + 2];
                A[(192 + c) * 64 + s] = fmaf(d1[0], v0, fmaf(d1[1], v1, d1[2] * v2));
                A[(64  + c) * 64 + s] = fmaf(d1[3], v0, fmaf(d1[4], v1, d1[5] * v2));
                A[(320 + c) * 64 + s] = fmaf(d1[6], v0, fmaf(d1[7], v1, d1[8] * v2));
                float u0 = br[256 + 5 * c],     u1 = br[256 + 5 * c + 1], u2 = br[256 + 5 * c + 2];
                float u3 = br[256 + 5 * c + 3], u4 = br[256 + 5 * c + 4];
                float rr[5];
                #pragma unroll
                for (int i = 0; i < 5; i++)
                    rr[i] = fmaf(d2[i*5+0], u0, fmaf(d2[i*5+1], u1, fmaf(d2[i*5+2], u2,
                            fmaf(d2[i*5+3], u3, d2[i*5+4] * u4))));
                A[(448 + c) * 64 + s] = rr[0];
                A[(256 + c) * 64 + s] = rr[1];
                A[(128 + c) * 64 + s] = rr[2];
                A[(384 + c) * 64 + s] = rr[3];
                A[(512 + c) * 64 + s] = rr[4];
            }
        }
        __syncthreads();
        if (p < 3) {
            const float* xp = xg + (p + 1) * 16 * 576;
            for (int idx = tid; idx < 16 * 576; idx += NTHR) {
                int s = idx / 576, d = idx % 576;
                ST[s * 577 + d] = xp[idx];
            }
            __syncthreads();
        }
    }

    // ---- Phase 2: register-tiled GEMMs, lane = output channel ----
    if (w < 8) {
        int og = w >> 1;
        int sgb = (w & 1) * 2;
        m1_tile(A, b, og, sgb,     lane, n0);
        m1_tile(A, b, og, sgb + 1, lane, n0);
    } else {
        int t = w - 8;
        if (t < 6) m0_tile(A, b, t >> 1, t & 1, lane, n0);
        m2_tile(A, b, t >> 2, t & 3, lane, n0);
    }
}

// Kernel 2: back-rotation.
#define K2THR 256
#define SM2_S   0
#define SM2_D1B (576 * 33)
#define SM2_D2B (SM2_D1B + 32 * 9)
#define SM2_TOT (SM2_D2B + 32 * 25)

__global__ __launch_bounds__(K2THR, 1)
void so2_backrot_kernel(const float* __restrict__ alpha,
                        const float* __restrict__ beta,
                        const float* __restrict__ gamma_,
                        const float* __restrict__ Jd1,
                        const float* __restrict__ Jd2,
                        float* __restrict__ out)
{
    extern __shared__ float sm[];
    float* S   = sm + SM2_S;
    float* D1b = sm + SM2_D1B;
    float* D2b = sm + SM2_D2B;

    const int tid  = threadIdx.x;
    const int w    = tid >> 5;
    const int lane = tid & 31;
    const int n0   = blockIdx.x * 32;

    for (int idx = tid; idx < 576 * 32; idx += K2THR) {
        int d = idx >> 5, s = idx & 31;
        S[d * 33 + s] = g_tmp[d * NSAMP + n0 + s];
    }
    if (tid < 32) {
        int n = n0 + tid;
        build_D(-gamma_[n], -beta[n], -alpha[n], Jd1, Jd2,
                D1b + tid * 9, D2b + tid * 25);
    }
    __syncthreads();

    {
        float e1[9], e2[25];
        #pragma unroll
        for (int j = 0; j < 9; j++)  e1[j] = D1b[lane * 9 + j];
        #pragma unroll
        for (int j = 0; j < 25; j++) e2[j] = D2b[lane * 25 + j];
        #pragma unroll
        for (int k = 0; k < 8; k++) {
            int c = w + 8 * k;
            float v0 = S[(64 + 3 * c) * 33 + lane];
            float v1 = S[(64 + 3 * c + 1) * 33 + lane];
            float v2 = S[(64 + 3 * c + 2) * 33 + lane];
            S[(64 + 3 * c) * 33 + lane]     = fmaf(e1[0], v0, fmaf(e1[1], v1, e1[2] * v2));
            S[(64 + 3 * c + 1) * 33 + lane] = fmaf(e1[3], v0, fmaf(e1[4], v1, e1[5] * v2));
            S[(64 + 3 * c + 2) * 33 + lane] = fmaf(e1[6], v0, fmaf(e1[7], v1, e1[8] * v2));
            float u0 = S[(256 + 5 * c) * 33 + lane];
            float u1 = S[(256 + 5 * c + 1) * 33 + lane];
            float u2 = S[(256 + 5 * c + 2) * 33 + lane];
            float u3 = S[(256 + 5 * c + 3) * 33 + lane];
            float u4 = S[(256 + 5 * c + 4) * 33 + lane];
            #pragma unroll
            for (int i = 0; i < 5; i++)
                S[(256 + 5 * c + i) * 33 + lane] =
                    fmaf(e2[i*5+0], u0, fmaf(e2[i*5+1], u1, fmaf(e2[i*5+2], u2,
                    fmaf(e2[i*5+3], u3, e2[i*5+4] * u4))));
        }
    }
    __syncthreads();

    for (int idx = tid; idx < 32 * 576; idx += K2THR) {
        int s = idx / 576, d = idx % 576;
        out[(size_t)(n0 + s) * 576 + d] = S[d * 33 + s];
    }
}

extern "C" void kernel_launch(void* const* d_in, const int* in_sizes, int n_in,
                              void* d_out, int out_size)
{
    const float* x     = (const float*)d_in[0];
    const float* alpha = (const float*)d_in[1];
    const float* beta  = (const float*)d_in[2];
    const float* gamma_= (const float*)d_in[3];
    const float* coef  = (const float*)d_in[4];
    const float* Jd1   = (const float*)d_in[5];
    const float* Jd2   = (const float*)d_in[6];
    const float* w0    = (const float*)d_in[7];
    const float* b0    = (const float*)d_in[8];
    const float* ws0   = (const float*)d_in[9];
    const float* bs0   = (const float*)d_in[10];
    const float* w1    = (const float*)d_in[11];
    const float* ws1   = (const float*)d_in[12];
    const float* w2    = (const float*)d_in[13];
    const float* ws2   = (const float*)d_in[14];
    float* out = (float*)d_out;

    const int totalW = 8 * 192 * 192 + 8 * 192 + 8 * 128 * 256 + 8 * 64 * 128;
    prep_weights_kernel<<<(totalW + 255) / 256, 256>>>(coef, w0, b0, ws0, bs0,
                                                       w1, ws1, w2, ws2);

    const int smem1 = SM1_TOT * sizeof(float);
    cudaFuncSetAttribute(so2_gemm_kernel,
                         cudaFuncAttributeMaxDynamicSharedMemorySize, smem1);
    so2_gemm_kernel<<<NSAMP / TILE, NTHR, smem1>>>(x, alpha, beta, gamma_, Jd1, Jd2);

    const int smem2 = SM2_TOT * sizeof(float);
    cudaFuncSetAttribute(so2_backrot_kernel,
                         cudaFuncAttributeMaxDynamicSharedMemorySize, smem2);
    so2_backrot_kernel<<<NSAMP / 32, K2THR, smem2>>>(alpha, beta, gamma_,
                                                     Jd1, Jd2, out);
}

// round 13
// speedup vs baseline: 1.4631x; 1.1043x over previous
#include <cuda_runtime.h>
#include <math.h>

#define NSAMP 64000
#define TILE  64
#define NTHR  512
#define SPB   8000

typedef unsigned long long ull;

__device__ __align__(16) float g_Wt0[8 * 192 * 192];
__device__ __align__(16) float g_bc0[8 * 192];
__device__ __align__(16) float g_Wt1[8 * 128 * 256];
__device__ __align__(16) float g_Wt2[8 * 64 * 128];
__device__ float g_tmp[576 * NSAMP];

// ---- packed fp32x2 FMA ----
__device__ __forceinline__ void ffma2(ull& a, ull w, ull x) {
    asm("fma.rn.f32x2 %0, %1, %2, %0;" : "+l"(a) : "l"(w), "l"(x));
}
__device__ __forceinline__ ull splat2(float w) {
    ull r; asm("mov.b64 %0, {%1, %1};" : "=l"(r) : "f"(w)); return r;
}
__device__ __forceinline__ float2 unpk(ull v) {
    float2 f; asm("mov.b64 {%0, %1}, %2;" : "=f"(f.x), "=f"(f.y) : "l"(v)); return f;
}

__global__ void prep_weights_kernel(
    const float* __restrict__ coef,
    const float* __restrict__ w0, const float* __restrict__ b0,
    const float* __restrict__ ws0, const float* __restrict__ bs0,
    const float* __restrict__ w1, const float* __restrict__ ws1,
    const float* __restrict__ w2, const float* __restrict__ ws2)
{
    int idx = blockIdx.x * blockDim.x + threadIdx.x;
    const int S0 = 8 * 192 * 192;
    const int S1 = 8 * 192;
    const int S2 = 8 * 128 * 256;
    const int S3 = 8 * 64 * 128;
    if (idx < S0) {
        int b = idx / 36864, r = idx % 36864;
        int i = r / 192, o = r % 192;
        float v = ws0[o * 192 + i];
        #pragma unroll
        for (int e = 0; e < 8; e++)
            v = fmaf(coef[b * 8 + e], w0[e * 36864 + o * 192 + i], v);
        g_Wt0[b * 36864 + i * 192 + o] = v;
        return;
    }
    idx -= S0;
    if (idx < S1) {
        int b = idx / 192, o = idx % 192;
        float v = bs0[o];
        #pragma unroll
        for (int e = 0; e < 8; e++)
            v = fmaf(coef[b * 8 + e], b0[e * 192 + o], v);
        g_bc0[b * 192 + o] = v;
        return;
    }
    idx -= S1;
    if (idx < S2) {
        int b = idx / 32768, r = idx % 32768;
        int i = r / 256, o = r % 256;
        float v = ws1[o * 128 + i];
        #pragma unroll
        for (int e = 0; e < 8; e++)
            v = fmaf(coef[b * 8 + e], w1[e * 32768 + o * 128 + i], v);
        g_Wt1[b * 32768 + i * 256 + o] = v;
        return;
    }
    idx -= S2;
    if (idx < S3) {
        int b = idx / 8192, r = idx % 8192;
        int i = r / 128, o = r % 128;
        float v = ws2[o * 64 + i];
        #pragma unroll
        for (int e = 0; e < 8; e++)
            v = fmaf(coef[b * 8 + e], w2[e * 8192 + o * 64 + i], v);
        g_Wt2[b * 8192 + i * 128 + o] = v;
    }
}

__device__ __forceinline__ void mm3(const float* P, const float* Q, float* R) {
    #pragma unroll
    for (int i = 0; i < 3; i++)
        #pragma unroll
        for (int j = 0; j < 3; j++) {
            float acc = 0.f;
            #pragma unroll
            for (int k = 0; k < 3; k++) acc = fmaf(P[i * 3 + k], Q[k * 3 + j], acc);
            R[i * 3 + j] = acc;
        }
}
__device__ __forceinline__ void mm5(const float* P, const float* Q, float* R) {
    #pragma unroll
    for (int i = 0; i < 5; i++)
        #pragma unroll
        for (int j = 0; j < 5; j++) {
            float acc = 0.f;
            #pragma unroll
            for (int k = 0; k < 5; k++) acc = fmaf(P[i * 5 + k], Q[k * 5 + j], acc);
            R[i * 5 + j] = acc;
        }
}

__device__ void build_D(float a1, float a2, float a3,
                        const float* __restrict__ J1g,
                        const float* __restrict__ J2g,
                        float* __restrict__ D1, float* __restrict__ D2)
{
    float J1[9], J2[25];
    #pragma unroll
    for (int i = 0; i < 9; i++) J1[i] = J1g[i];
    #pragma unroll
    for (int i = 0; i < 25; i++) J2[i] = J2g[i];

    float X[3][9], Y[3][25];
    float aa[3] = {a1, a2, a3};
    #pragma unroll
    for (int t = 0; t < 3; t++) {
        float c1, s1, c2, s2;
        sincosf(aa[t], &s1, &c1);
        sincosf(2.0f * aa[t], &s2, &c2);
        float* Xp = X[t];
        Xp[0] = c1;  Xp[1] = 0.f; Xp[2] = s1;
        Xp[3] = 0.f; Xp[4] = 1.f; Xp[5] = 0.f;
        Xp[6] = -s1; Xp[7] = 0.f; Xp[8] = c1;
        float* Yp = Y[t];
        #pragma unroll
        for (int q = 0; q < 25; q++) Yp[q] = 0.f;
        Yp[0]  = c2;  Yp[4]  = s2;
        Yp[6]  = c1;  Yp[8]  = s1;
        Yp[12] = 1.f;
        Yp[16] = -s1; Yp[18] = c1;
        Yp[20] = -s2; Yp[24] = c2;
    }
    float T1[9], T2[9];
    mm3(X[0], J1, T1);
    mm3(T1, X[1], T2);
    mm3(T2, J1, T1);
    mm3(T1, X[2], D1);
    float U1[25], U2[25];
    mm5(Y[0], J2, U1);
    mm5(U1, Y[1], U2);
    mm5(U2, J2, U1);
    mm5(U1, Y[2], D2);
}

// Kernel 1 SMEM (floats): A[576*64] plain [dim][s]; ST[16*577]; D1f/D2f
#define SM_A    0
#define SM_ST   (576 * 64)
#define SM_D1F  (SM_ST + 16 * 577)
#define SM_D2F  (SM_D1F + 64 * 9)
#define SM1_TOT (SM_D2F + 64 * 25)

// ---- warp tiles: lane = output channel, double-buffered weight prefetch ----

// m0: 64 outputs x 32 samples, K=192, k-chunks of 4
__device__ __forceinline__ void m0_tile(const float* __restrict__ A, int b,
                                        int og, int sh, int lane, int n0)
{
    int o0 = og * 64;
    int s0 = sh * 32;
    const float* wp = g_Wt0 + b * 36864 + o0 + lane;
    float bv0 = g_bc0[b * 192 + o0 + lane];
    float bv1 = g_bc0[b * 192 + o0 + 32 + lane];
    ull a0[16], a1[16];
    #pragma unroll
    for (int j = 0; j < 16; j++) { a0[j] = splat2(bv0); a1[j] = splat2(bv1); }
    float w0b[2][4], w1b[2][4];
    #pragma unroll
    for (int j = 0; j < 4; j++) {
        w0b[0][j] = wp[j * 192];
        w1b[0][j] = wp[j * 192 + 32];
    }
    int cur = 0;
    #pragma unroll 1
    for (int k0 = 0; k0 < 192; k0 += 4) {
        int nxt = cur ^ 1;
        if (k0 + 4 < 192) {
            #pragma unroll
            for (int j = 0; j < 4; j++) {
                w0b[nxt][j] = wp[(k0 + 4 + j) * 192];
                w1b[nxt][j] = wp[(k0 + 4 + j) * 192 + 32];
            }
        }
        #pragma unroll
        for (int j = 0; j < 4; j++) {
            ull w0u = splat2(w0b[cur][j]);
            ull w1u = splat2(w1b[cur][j]);
            const ulonglong2* xv = (const ulonglong2*)(A + (k0 + j) * 64 + s0);
            #pragma unroll
            for (int q = 0; q < 8; q++) {
                ulonglong2 xx = xv[q];
                ffma2(a0[2 * q],     w0u, xx.x);
                ffma2(a0[2 * q + 1], w0u, xx.y);
                ffma2(a1[2 * q],     w1u, xx.x);
                ffma2(a1[2 * q + 1], w1u, xx.y);
            }
        }
        cur = nxt;
    }
    #pragma unroll
    for (int h = 0; h < 2; h++) {
        int o = o0 + 32 * h + lane;
        int dim = (o < 64) ? o : (o < 128) ? (3 * o - 127) : (5 * o - 382);
        float* gp = g_tmp + (size_t)dim * NSAMP + n0 + s0;
        ull* ap = h ? a1 : a0;
        #pragma unroll
        for (int t = 0; t < 8; t++) {
            float2 p0 = unpk(ap[2 * t]), p1 = unpk(ap[2 * t + 1]);
            *reinterpret_cast<float4*>(gp + 4 * t) =
                make_float4(p0.x, p0.y, p1.x, p1.y);
        }
    }
}

// m1: 32 output-pairs x 16 samples x 2 input cols, K=128, k-chunks of 4
// 16 samples = 4 ulonglong2 loads (q<4), slots 2*q, 2*q+1  (FIXED vs R12)
__device__ __forceinline__ void m1_tile(const float* __restrict__ A, int b,
                                        int og, int sg, int lane, int n0)
{
    int o0 = og * 32;
    int s0 = sg * 16;
    const float* wp = g_Wt1 + b * 32768 + o0 + lane;
    ull yr0[8], yr1[8], yi0[8], yi1[8];
    #pragma unroll
    for (int j = 0; j < 8; j++) { yr0[j] = yr1[j] = yi0[j] = yi1[j] = 0ull; }
    float wrb[2][4], wib[2][4];
    #pragma unroll
    for (int j = 0; j < 4; j++) {
        wrb[0][j] = wp[j * 256];
        wib[0][j] = wp[j * 256 + 128];
    }
    int cur = 0;
    #pragma unroll 1
    for (int k0 = 0; k0 < 128; k0 += 4) {
        int nxt = cur ^ 1;
        if (k0 + 4 < 128) {
            #pragma unroll
            for (int j = 0; j < 4; j++) {
                wrb[nxt][j] = wp[(k0 + 4 + j) * 256];
                wib[nxt][j] = wp[(k0 + 4 + j) * 256 + 128];
            }
        }
        #pragma unroll
        for (int j = 0; j < 4; j++) {
            ull wru = splat2(wrb[cur][j]);
            ull wiu = splat2(wib[cur][j]);
            const ulonglong2* x0v = (const ulonglong2*)(A + (192 + k0 + j) * 64 + s0);
            const ulonglong2* x1v = (const ulonglong2*)(A + (320 + k0 + j) * 64 + s0);
            #pragma unroll
            for (int q = 0; q < 4; q++) {
                ulonglong2 x0 = x0v[q], x1 = x1v[q];
                ffma2(yr0[2 * q],     wru, x0.x);
                ffma2(yr0[2 * q + 1], wru, x0.y);
                ffma2(yr1[2 * q],     wru, x1.x);
                ffma2(yr1[2 * q + 1], wru, x1.y);
                ffma2(yi0[2 * q],     wiu, x0.x);
                ffma2(yi0[2 * q + 1], wiu, x0.y);
                ffma2(yi1[2 * q],     wiu, x1.x);
                ffma2(yi1[2 * q + 1], wiu, x1.y);
            }
        }
        cur = nxt;
    }
    int k = o0 + lane;
    int dm = (k < 64) ? (64 + 3 * k) : (256 + 5 * (k - 64) + 1);
    int dp = dm + 2;
    float* gm = g_tmp + (size_t)dm * NSAMP + n0 + s0;
    float* gp = g_tmp + (size_t)dp * NSAMP + n0 + s0;
    #pragma unroll
    for (int t = 0; t < 4; t++) {
        float2 r0a = unpk(yr0[2 * t]), r0b = unpk(yr0[2 * t + 1]);
        float2 r1a = unpk(yr1[2 * t]), r1b = unpk(yr1[2 * t + 1]);
        float2 i0a = unpk(yi0[2 * t]), i0b = unpk(yi0[2 * t + 1]);
        float2 i1a = unpk(yi1[2 * t]), i1b = unpk(yi1[2 * t + 1]);
        *reinterpret_cast<float4*>(gm + 4 * t) = make_float4(
            r0a.x - i1a.x, r0a.y - i1a.y, r0b.x - i1b.x, r0b.y - i1b.y);
        *reinterpret_cast<float4*>(gp + 4 * t) = make_float4(
            r1a.x + i0a.x, r1a.y + i0a.y, r1b.x + i0b.x, r1b.y + i0b.y);
    }
}

// m2: 32 output-pairs x 16 samples x 2 input cols, K=64, k-chunks of 4
// 16 samples = 4 ulonglong2 loads (q<4), slots 2*q, 2*q+1  (FIXED vs R12)
__device__ __forceinline__ void m2_tile(const float* __restrict__ A, int b,
                                        int og, int sg, int lane, int n0)
{
    int o0 = og * 32;
    int s0 = sg * 16;
    const float* wp = g_Wt2 + b * 8192 + o0 + lane;
    ull yr0[8], yr1[8], yi0[8], yi1[8];
    #pragma unroll
    for (int j = 0; j < 8; j++) { yr0[j] = yr1[j] = yi0[j] = yi1[j] = 0ull; }
    float wrb[2][4], wib[2][4];
    #pragma unroll
    for (int j = 0; j < 4; j++) {
        wrb[0][j] = wp[j * 128];
        wib[0][j] = wp[j * 128 + 64];
    }
    int cur = 0;
    #pragma unroll 1
    for (int k0 = 0; k0 < 64; k0 += 4) {
        int nxt = cur ^ 1;
        if (k0 + 4 < 64) {
            #pragma unroll
            for (int j = 0; j < 4; j++) {
                wrb[nxt][j] = wp[(k0 + 4 + j) * 128];
                wib[nxt][j] = wp[(k0 + 4 + j) * 128 + 64];
            }
        }
        #pragma unroll
        for (int j = 0; j < 4; j++) {
            ull wru = splat2(wrb[cur][j]);
            ull wiu = splat2(wib[cur][j]);
            const ulonglong2* x0v = (const ulonglong2*)(A + (448 + k0 + j) * 64 + s0);
            const ulonglong2* x1v = (const ulonglong2*)(A + (512 + k0 + j) * 64 + s0);
            #pragma unroll
            for (int q = 0; q < 4; q++) {
                ulonglong2 x0 = x0v[q], x1 = x1v[q];
                ffma2(yr0[2 * q],     wru, x0.x);
                ffma2(yr0[2 * q + 1], wru, x0.y);
                ffma2(yr1[2 * q],     wru, x1.x);
                ffma2(yr1[2 * q + 1], wru, x1.y);
                ffma2(yi0[2 * q],     wiu, x0.x);
                ffma2(yi0[2 * q + 1], wiu, x0.y);
                ffma2(yi1[2 * q],     wiu, x1.x);
                ffma2(yi1[2 * q + 1], wiu, x1.y);
            }
        }
        cur = nxt;
    }
    int k = o0 + lane;
    int dm = 256 + 5 * k;
    int dp = dm + 4;
    float* gm = g_tmp + (size_t)dm * NSAMP + n0 + s0;
    float* gp = g_tmp + (size_t)dp * NSAMP + n0 + s0;
    #pragma unroll
    for (int t = 0; t < 4; t++) {
        float2 r0a = unpk(yr0[2 * t]), r0b = unpk(yr0[2 * t + 1]);
        float2 r1a = unpk(yr1[2 * t]), r1b = unpk(yr1[2 * t + 1]);
        float2 i0a = unpk(yi0[2 * t]), i0b = unpk(yi0[2 * t + 1]);
        float2 i1a = unpk(yi1[2 * t]), i1b = unpk(yi1[2 * t + 1]);
        *reinterpret_cast<float4*>(gm + 4 * t) = make_float4(
            r0a.x - i1a.x, r0a.y - i1a.y, r0b.x - i1b.x, r0b.y - i1b.y);
        *reinterpret_cast<float4*>(gp + 4 * t) = make_float4(
            r1a.x + i0a.x, r1a.y + i0a.y, r1b.x + i0b.x, r1b.y + i0b.y);
    }
}

__global__ __launch_bounds__(NTHR, 1)
void so2_gemm_kernel(const float* __restrict__ x,
                     const float* __restrict__ alpha,
                     const float* __restrict__ beta,
                     const float* __restrict__ gamma_,
                     const float* __restrict__ Jd1,
                     const float* __restrict__ Jd2)
{
    extern __shared__ float sm[];
    float* A   = sm + SM_A;
    float* ST  = sm + SM_ST;
    float* D1f = sm + SM_D1F;
    float* D2f = sm + SM_D2F;

    const int tid  = threadIdx.x;
    const int w    = tid >> 5;
    const int lane = tid & 31;
    const int n0   = blockIdx.x * TILE;
    const int b    = n0 / SPB;
    const float* xg = x + (size_t)n0 * 576;

    // ---- Phase 1: fwd Wigner (threads 0-63) + stage pass 0 ----
    if (tid < 64) {
        int n = n0 + tid;
        build_D(alpha[n], beta[n], gamma_[n], Jd1, Jd2,
                D1f + tid * 9, D2f + tid * 25);
    } else {
        for (int idx = tid - 64; idx < 16 * 576; idx += NTHR - 64) {
            int s = idx / 576, d = idx % 576;
            ST[s * 577 + d] = xg[idx];
        }
    }
    __syncthreads();

    // ---- 4 passes: gather+rotate 16 samples, then stage next 16 ----
    for (int p = 0; p < 4; p++) {
        {
            int s16 = tid & 15;
            int grp = tid >> 4;
            int s   = p * 16 + s16;
            const float* br = ST + s16 * 577;
            float d1[9], d2[25];
            #pragma unroll
            for (int j = 0; j < 9; j++)  d1[j] = D1f[s * 9 + j];
            #pragma unroll
            for (int j = 0; j < 25; j++) d2[j] = D2f[s * 25 + j];
            #pragma unroll
            for (int cc = 0; cc < 2; cc++) {
                int c = grp + 32 * cc;
                A[c * 64 + s] = br[c];
                float v0 = br[64 + 3 * c], v1 = br[64 + 3 * c + 1], v2 = br[64 + 3 * c + 2];
                A[(192 + c) * 64 + s] = fmaf(d1[0], v0, fmaf(d1[1], v1, d1[2] * v2));
                A[(64  + c) * 64 + s] = fmaf(d1[3], v0, fmaf(d1[4], v1, d1[5] * v2));
                A[(320 + c) * 64 + s] = fmaf(d1[6], v0, fmaf(d1[7], v1, d1[8] * v2));
                float u0 = br[256 + 5 * c],     u1 = br[256 + 5 * c + 1], u2 = br[256 + 5 * c + 2];
                float u3 = br[256 + 5 * c + 3], u4 = br[256 + 5 * c + 4];
                float rr[5];
                #pragma unroll
                for (int i = 0; i < 5; i++)
                    rr[i] = fmaf(d2[i*5+0], u0, fmaf(d2[i*5+1], u1, fmaf(d2[i*5+2], u2,
                            fmaf(d2[i*5+3], u3, d2[i*5+4] * u4))));
                A[(448 + c) * 64 + s] = rr[0];
                A[(256 + c) * 64 + s] = rr[1];
                A[(128 + c) * 64 + s] = rr[2];
                A[(384 + c) * 64 + s] = rr[3];
                A[(512 + c) * 64 + s] = rr[4];
            }
        }
        __syncthreads();
        if (p < 3) {
            const float* xp = xg + (p + 1) * 16 * 576;
            for (int idx = tid; idx < 16 * 576; idx += NTHR) {
                int s = idx / 576, d = idx % 576;
                ST[s * 577 + d] = xp[idx];
            }
            __syncthreads();
        }
    }

    // ---- Phase 2: register-tiled GEMMs, lane = output channel ----
    if (w < 8) {
        int og = w >> 1;
        int sgb = (w & 1) * 2;
        m1_tile(A, b, og, sgb,     lane, n0);
        m1_tile(A, b, og, sgb + 1, lane, n0);
    } else {
        int t = w - 8;
        if (t < 6) m0_tile(A, b, t >> 1, t & 1, lane, n0);
        m2_tile(A, b, t >> 2, t & 3, lane, n0);
    }
}

// Kernel 2: back-rotation.
#define K2THR 256
#define SM2_S   0
#define SM2_D1B (576 * 33)
#define SM2_D2B (SM2_D1B + 32 * 9)
#define SM2_TOT (SM2_D2B + 32 * 25)

__global__ __launch_bounds__(K2THR, 1)
void so2_backrot_kernel(const float* __restrict__ alpha,
                        const float* __restrict__ beta,
                        const float* __restrict__ gamma_,
                        const float* __restrict__ Jd1,
                        const float* __restrict__ Jd2,
                        float* __restrict__ out)
{
    extern __shared__ float sm[];
    float* S   = sm + SM2_S;
    float* D1b = sm + SM2_D1B;
    float* D2b = sm + SM2_D2B;

    const int tid  = threadIdx.x;
    const int w    = tid >> 5;
    const int lane = tid & 31;
    const int n0   = blockIdx.x * 32;

    for (int idx = tid; idx < 576 * 32; idx += K2THR) {
        int d = idx >> 5, s = idx & 31;
        S[d * 33 + s] = g_tmp[d * NSAMP + n0 + s];
    }
    if (tid < 32) {
        int n = n0 + tid;
        build_D(-gamma_[n], -beta[n], -alpha[n], Jd1, Jd2,
                D1b + tid * 9, D2b + tid * 25);
    }
    __syncthreads();

    {
        float e1[9], e2[25];
        #pragma unroll
        for (int j = 0; j < 9; j++)  e1[j] = D1b[lane * 9 + j];
        #pragma unroll
        for (int j = 0; j < 25; j++) e2[j] = D2b[lane * 25 + j];
        #pragma unroll
        for (int k = 0; k < 8; k++) {
            int c = w + 8 * k;
            float v0 = S[(64 + 3 * c) * 33 + lane];
            float v1 = S[(64 + 3 * c + 1) * 33 + lane];
            float v2 = S[(64 + 3 * c + 2) * 33 + lane];
            S[(64 + 3 * c) * 33 + lane]     = fmaf(e1[0], v0, fmaf(e1[1], v1, e1[2] * v2));
            S[(64 + 3 * c + 1) * 33 + lane] = fmaf(e1[3], v0, fmaf(e1[4], v1, e1[5] * v2));
            S[(64 + 3 * c + 2) * 33 + lane] = fmaf(e1[6], v0, fmaf(e1[7], v1, e1[8] * v2));
            float u0 = S[(256 + 5 * c) * 33 + lane];
            float u1 = S[(256 + 5 * c + 1) * 33 + lane];
            float u2 = S[(256 + 5 * c + 2) * 33 + lane];
            float u3 = S[(256 + 5 * c + 3) * 33 + lane];
            float u4 = S[(256 + 5 * c + 4) * 33 + lane];
            #pragma unroll
            for (int i = 0; i < 5; i++)
                S[(256 + 5 * c + i) * 33 + lane] =
                    fmaf(e2[i*5+0], u0, fmaf(e2[i*5+1], u1, fmaf(e2[i*5+2], u2,
                    fmaf(e2[i*5+3], u3, e2[i*5+4] * u4))));
        }
    }
    __syncthreads();

    for (int idx = tid; idx < 32 * 576; idx += K2THR) {
        int s = idx / 576, d = idx % 576;
        out[(size_t)(n0 + s) * 576 + d] = S[d * 33 + s];
    }
}

extern "C" void kernel_launch(void* const* d_in, const int* in_sizes, int n_in,
                              void* d_out, int out_size)
{
    const float* x     = (const float*)d_in[0];
    const float* alpha = (const float*)d_in[1];
    const float* beta  = (const float*)d_in[2];
    const float* gamma_= (const float*)d_in[3];
    const float* coef  = (const float*)d_in[4];
    const float* Jd1   = (const float*)d_in[5];
    const float* Jd2   = (const float*)d_in[6];
    const float* w0    = (const float*)d_in[7];
    const float* b0    = (const float*)d_in[8];
    const float* ws0   = (const float*)d_in[9];
    const float* bs0   = (const float*)d_in[10];
    const float* w1    = (const float*)d_in[11];
    const float* ws1   = (const float*)d_in[12];
    const float* w2    = (const float*)d_in[13];
    const float* ws2   = (const float*)d_in[14];
    float* out = (float*)d_out;

    const int totalW = 8 * 192 * 192 + 8 * 192 + 8 * 128 * 256 + 8 * 64 * 128;
    prep_weights_kernel<<<(totalW + 255) / 256, 256>>>(coef, w0, b0, ws0, bs0,
                                                       w1, ws1, w2, ws2);

    const int smem1 = SM1_TOT * sizeof(float);
    cudaFuncSetAttribute(so2_gemm_kernel,
                         cudaFuncAttributeMaxDynamicSharedMemorySize, smem1);
    so2_gemm_kernel<<<NSAMP / TILE, NTHR, smem1>>>(x, alpha, beta, gamma_, Jd1, Jd2);

    const int smem2 = SM2_TOT * sizeof(float);
    cudaFuncSetAttribute(so2_backrot_kernel,
                         cudaFuncAttributeMaxDynamicSharedMemorySize, smem2);
    so2_backrot_kernel<<<NSAMP / 32, K2THR, smem2>>>(alpha, beta, gamma_,
                                                     Jd1, Jd2, out);
}

// round 14
// speedup vs baseline: 1.8405x; 1.2580x over previous
#include <cuda_runtime.h>
#include <math.h>
#include <stdint.h>

#define NSAMP 64000
#define TILE  64
#define NTHR  512
#define SPB   8000

// tf32 hi/lo split weights, [b][i][o] layout (i = input chan, o = output)
__device__ __align__(16) float g_W0h[8 * 192 * 192];
__device__ __align__(16) float g_W0l[8 * 192 * 192];
__device__ __align__(16) float g_W1h[8 * 128 * 256];
__device__ __align__(16) float g_W1l[8 * 128 * 256];
__device__ __align__(16) float g_W2h[8 * 64 * 128];
__device__ __align__(16) float g_W2l[8 * 64 * 128];
__device__ __align__(16) float g_bc0[8 * 192];
__device__ float g_tmp[576 * NSAMP];

__device__ __forceinline__ uint32_t tf32_rna(float x) {
    uint32_t r; asm("cvt.rna.tf32.f32 %0, %1;" : "=r"(r) : "f"(x)); return r;
}
// split x -> hi (tf32 bits) and lo (tf32 bits of remainder)
__device__ __forceinline__ void tf32_split(float x, uint32_t& hi, uint32_t& lo) {
    hi = tf32_rna(x);
    float rem = x - __uint_as_float(hi);
    lo = tf32_rna(rem);
}

__device__ __forceinline__ void mma8(float* d, const uint32_t* a, const uint32_t* b) {
    asm("mma.sync.aligned.m16n8k8.row.col.f32.tf32.tf32.f32 "
        "{%0,%1,%2,%3},{%4,%5,%6,%7},{%8,%9},{%0,%1,%2,%3};"
        : "+f"(d[0]), "+f"(d[1]), "+f"(d[2]), "+f"(d[3])
        : "r"(a[0]), "r"(a[1]), "r"(a[2]), "r"(a[3]), "r"(b[0]), "r"(b[1]));
}
// 3xTF32: acc += Ahi*Bhi + Ahi*Blo + Alo*Bhi
__device__ __forceinline__ void mma3x(float* d, const uint32_t* ah, const uint32_t* al,
                                      const uint32_t* bh, const uint32_t* bl) {
    mma8(d, ah, bh);
    mma8(d, ah, bl);
    mma8(d, al, bh);
}

__global__ void prep_weights_kernel(
    const float* __restrict__ coef,
    const float* __restrict__ w0, const float* __restrict__ b0,
    const float* __restrict__ ws0, const float* __restrict__ bs0,
    const float* __restrict__ w1, const float* __restrict__ ws1,
    const float* __restrict__ w2, const float* __restrict__ ws2)
{
    int idx = blockIdx.x * blockDim.x + threadIdx.x;
    const int S0 = 8 * 192 * 192;
    const int S1 = 8 * 192;
    const int S2 = 8 * 128 * 256;
    const int S3 = 8 * 64 * 128;
    if (idx < S0) {
        int b = idx / 36864, r = idx % 36864;
        int i = r / 192, o = r % 192;
        float v = ws0[o * 192 + i];
        #pragma unroll
        for (int e = 0; e < 8; e++)
            v = fmaf(coef[b * 8 + e], w0[e * 36864 + o * 192 + i], v);
        uint32_t hi, lo; tf32_split(v, hi, lo);
        g_W0h[b * 36864 + i * 192 + o] = __uint_as_float(hi);
        g_W0l[b * 36864 + i * 192 + o] = __uint_as_float(lo);
        return;
    }
    idx -= S0;
    if (idx < S1) {
        int b = idx / 192, o = idx % 192;
        float v = bs0[o];
        #pragma unroll
        for (int e = 0; e < 8; e++)
            v = fmaf(coef[b * 8 + e], b0[e * 192 + o], v);
        g_bc0[b * 192 + o] = v;
        return;
    }
    idx -= S1;
    if (idx < S2) {
        int b = idx / 32768, r = idx % 32768;
        int i = r / 256, o = r % 256;
        float v = ws1[o * 128 + i];
        #pragma unroll
        for (int e = 0; e < 8; e++)
            v = fmaf(coef[b * 8 + e], w1[e * 32768 + o * 128 + i], v);
        uint32_t hi, lo; tf32_split(v, hi, lo);
        g_W1h[b * 32768 + i * 256 + o] = __uint_as_float(hi);
        g_W1l[b * 32768 + i * 256 + o] = __uint_as_float(lo);
        return;
    }
    idx -= S2;
    if (idx < S3) {
        int b = idx / 8192, r = idx % 8192;
        int i = r / 128, o = r % 128;
        float v = ws2[o * 64 + i];
        #pragma unroll
        for (int e = 0; e < 8; e++)
            v = fmaf(coef[b * 8 + e], w2[e * 8192 + o * 64 + i], v);
        uint32_t hi, lo; tf32_split(v, hi, lo);
        g_W2h[b * 8192 + i * 128 + o] = __uint_as_float(hi);
        g_W2l[b * 8192 + i * 128 + o] = __uint_as_float(lo);
    }
}

__device__ __forceinline__ void mm3(const float* P, const float* Q, float* R) {
    #pragma unroll
    for (int i = 0; i < 3; i++)
        #pragma unroll
        for (int j = 0; j < 3; j++) {
            float acc = 0.f;
            #pragma unroll
            for (int k = 0; k < 3; k++) acc = fmaf(P[i * 3 + k], Q[k * 3 + j], acc);
            R[i * 3 + j] = acc;
        }
}
__device__ __forceinline__ void mm5(const float* P, const float* Q, float* R) {
    #pragma unroll
    for (int i = 0; i < 5; i++)
        #pragma unroll
        for (int j = 0; j < 5; j++) {
            float acc = 0.f;
            #pragma unroll
            for (int k = 0; k < 5; k++) acc = fmaf(P[i * 5 + k], Q[k * 5 + j], acc);
            R[i * 5 + j] = acc;
        }
}

__device__ void build_D(float a1, float a2, float a3,
                        const float* __restrict__ J1g,
                        const float* __restrict__ J2g,
                        float* __restrict__ D1, float* __restrict__ D2)
{
    float J1[9], J2[25];
    #pragma unroll
    for (int i = 0; i < 9; i++) J1[i] = J1g[i];
    #pragma unroll
    for (int i = 0; i < 25; i++) J2[i] = J2g[i];

    float X[3][9], Y[3][25];
    float aa[3] = {a1, a2, a3};
    #pragma unroll
    for (int t = 0; t < 3; t++) {
        float c1, s1, c2, s2;
        sincosf(aa[t], &s1, &c1);
        sincosf(2.0f * aa[t], &s2, &c2);
        float* Xp = X[t];
        Xp[0] = c1;  Xp[1] = 0.f; Xp[2] = s1;
        Xp[3] = 0.f; Xp[4] = 1.f; Xp[5] = 0.f;
        Xp[6] = -s1; Xp[7] = 0.f; Xp[8] = c1;
        float* Yp = Y[t];
        #pragma unroll
        for (int q = 0; q < 25; q++) Yp[q] = 0.f;
        Yp[0]  = c2;  Yp[4]  = s2;
        Yp[6]  = c1;  Yp[8]  = s1;
        Yp[12] = 1.f;
        Yp[16] = -s1; Yp[18] = c1;
        Yp[20] = -s2; Yp[24] = c2;
    }
    float T1[9], T2[9];
    mm3(X[0], J1, T1);
    mm3(T1, X[1], T2);
    mm3(T2, J1, T1);
    mm3(T1, X[2], D1);
    float U1[25], U2[25];
    mm5(Y[0], J2, U1);
    mm5(U1, Y[1], U2);
    mm5(U2, J2, U1);
    mm5(U1, Y[2], D2);
}

// Kernel 1 SMEM: A[64][580] ([sample][gdim], stride 580 = 4 mod 32 ->
// conflict-free mma A-fragment loads); ST[16*577]; D1f/D2f.
#define ASTR    580
#define SM_A    0
#define SM_ST   (64 * ASTR)
#define SM_D1F  (SM_ST + 16 * 577)
#define SM_D2F  (SM_D1F + 64 * 9)
#define SM1_TOT (SM_D2F + 64 * 25)

// A fragment load + tf32 split. chan = gdim base of this group's k-range.
__device__ __forceinline__ void load_a_frag(const float* __restrict__ A,
                                            int mrow0, int chan, int k0,
                                            int g, int t,
                                            uint32_t* ah, uint32_t* al)
{
    const float* ap = A + (mrow0 + g) * ASTR + chan + k0;
    float a0 = ap[t];
    float a1 = ap[8 * ASTR + t];
    float a2 = ap[t + 4];
    float a3 = ap[8 * ASTR + t + 4];
    tf32_split(a0, ah[0], al[0]);
    tf32_split(a1, ah[1], al[1]);
    tf32_split(a2, ah[2], al[2]);
    tf32_split(a3, ah[3], al[3]);
}

// B fragment load from pre-split hi/lo weight arrays.
__device__ __forceinline__ void load_b_frag(const float* __restrict__ Wh,
                                            const float* __restrict__ Wl,
                                            int ldo, int k0, int o0,
                                            int g, int t,
                                            uint32_t* bh, uint32_t* bl)
{
    const float* ph = Wh + (k0 + t) * ldo + o0 + g;
    const float* pl = Wl + (k0 + t) * ldo + o0 + g;
    bh[0] = __float_as_uint(ph[0]);
    bh[1] = __float_as_uint(ph[4 * ldo]);
    bl[0] = __float_as_uint(pl[0]);
    bl[1] = __float_as_uint(pl[4 * ldo]);
}

__global__ __launch_bounds__(NTHR, 1)
void so2_gemm_kernel(const float* __restrict__ x,
                     const float* __restrict__ alpha,
                     const float* __restrict__ beta,
                     const float* __restrict__ gamma_,
                     const float* __restrict__ Jd1,
                     const float* __restrict__ Jd2)
{
    extern __shared__ float sm[];
    float* A   = sm + SM_A;
    float* ST  = sm + SM_ST;
    float* D1f = sm + SM_D1F;
    float* D2f = sm + SM_D2F;

    const int tid  = threadIdx.x;
    const int w    = tid >> 5;
    const int lane = tid & 31;
    const int g    = lane >> 2;   // mma group id (rows / out cols)
    const int t    = lane & 3;    // thread-in-group (k / out pairs)
    const int n0   = blockIdx.x * TILE;
    const int b    = n0 / SPB;
    const float* xg = x + (size_t)n0 * 576;

    // ---- Phase 1: fwd Wigner (threads 0-63) + stage pass 0 ----
    if (tid < 64) {
        int n = n0 + tid;
        build_D(alpha[n], beta[n], gamma_[n], Jd1, Jd2,
                D1f + tid * 9, D2f + tid * 25);
    } else {
        for (int idx = tid - 64; idx < 16 * 576; idx += NTHR - 64) {
            int s = idx / 576, d = idx % 576;
            ST[s * 577 + d] = xg[idx];
        }
    }
    __syncthreads();

    // ---- 4 passes: gather+rotate 16 samples into A[s][gdim] ----
    for (int p = 0; p < 4; p++) {
        {
            int s16 = tid & 15;
            int grp = tid >> 4;
            int s   = p * 16 + s16;
            const float* br = ST + s16 * 577;
            float* As = A + s * ASTR;
            float d1[9], d2[25];
            #pragma unroll
            for (int j = 0; j < 9; j++)  d1[j] = D1f[s * 9 + j];
            #pragma unroll
            for (int j = 0; j < 25; j++) d2[j] = D2f[s * 25 + j];
            #pragma unroll
            for (int cc = 0; cc < 2; cc++) {
                int c = grp + 32 * cc;
                As[c] = br[c];
                float v0 = br[64 + 3 * c], v1 = br[64 + 3 * c + 1], v2 = br[64 + 3 * c + 2];
                As[192 + c] = fmaf(d1[0], v0, fmaf(d1[1], v1, d1[2] * v2));
                As[64  + c] = fmaf(d1[3], v0, fmaf(d1[4], v1, d1[5] * v2));
                As[320 + c] = fmaf(d1[6], v0, fmaf(d1[7], v1, d1[8] * v2));
                float u0 = br[256 + 5 * c],     u1 = br[256 + 5 * c + 1], u2 = br[256 + 5 * c + 2];
                float u3 = br[256 + 5 * c + 3], u4 = br[256 + 5 * c + 4];
                float rr[5];
                #pragma unroll
                for (int i = 0; i < 5; i++)
                    rr[i] = fmaf(d2[i*5+0], u0, fmaf(d2[i*5+1], u1, fmaf(d2[i*5+2], u2,
                            fmaf(d2[i*5+3], u3, d2[i*5+4] * u4))));
                As[448 + c] = rr[0];
                As[256 + c] = rr[1];
                As[128 + c] = rr[2];
                As[384 + c] = rr[3];
                As[512 + c] = rr[4];
            }
        }
        __syncthreads();
        if (p < 3) {
            const float* xp = xg + (p + 1) * 16 * 576;
            for (int idx = tid; idx < 16 * 576; idx += NTHR) {
                int s = idx / 576, d = idx % 576;
                ST[s * 577 + d] = xp[idx];
            }
            __syncthreads();
        }
    }

    // ---- Phase 2: 3xTF32 tensor-core GEMMs ----
    if (w < 8) {
        // m1: warp w, real outs [16w,16w+16), imag +128. K=128, O=256.
        const float* Wh = g_W1h + b * 32768;
        const float* Wl = g_W1l + b * 32768;
        int orb = 16 * w;
        int on[4] = { orb, orb + 8, 128 + orb, 136 + orb };  // r0 r1 i0 i1
        #pragma unroll 1
        for (int tt = 0; tt < 2; tt++) {
            float acc[2][2][4][4];  // [jj sample-tile][p x0/x1][n][c]
            #pragma unroll
            for (int jj = 0; jj < 2; jj++)
                #pragma unroll
                for (int pp = 0; pp < 2; pp++)
                    #pragma unroll
                    for (int nn = 0; nn < 4; nn++)
                        #pragma unroll
                        for (int c = 0; c < 4; c++) acc[jj][pp][nn][c] = 0.f;
            #pragma unroll 1
            for (int k0 = 0; k0 < 128; k0 += 8) {
                uint32_t Bh[4][2], Bl[4][2];
                #pragma unroll
                for (int nn = 0; nn < 4; nn++)
                    load_b_frag(Wh, Wl, 256, k0, on[nn], g, t, Bh[nn], Bl[nn]);
                #pragma unroll
                for (int jj = 0; jj < 2; jj++) {
                    int mrow0 = 16 * (2 * tt + jj);
                    #pragma unroll
                    for (int pp = 0; pp < 2; pp++) {
                        uint32_t Ah[4], Al[4];
                        load_a_frag(A, mrow0, pp ? 320 : 192, k0, g, t, Ah, Al);
                        #pragma unroll
                        for (int nn = 0; nn < 4; nn++)
                            mma3x(acc[jj][pp][nn], Ah, Al, Bh[nn], Bl[nn]);
                    }
                }
            }
            // epilogue: complex recombination + scatter
            #pragma unroll
            for (int jj = 0; jj < 2; jj++) {
                int sbase = 16 * (2 * tt + jj);
                #pragma unroll
                for (int nr = 0; nr < 2; nr++) {
                    #pragma unroll
                    for (int c = 0; c < 4; c++) {
                        int k = orb + 8 * nr + 2 * t + (c & 1);
                        int s = sbase + g + ((c >> 1) ? 8 : 0);
                        float om = acc[jj][0][nr][c]     - acc[jj][1][2 + nr][c];
                        float op = acc[jj][1][nr][c]     + acc[jj][0][2 + nr][c];
                        int dm = (k < 64) ? (64 + 3 * k) : (256 + 5 * (k - 64) + 1);
                        g_tmp[(size_t)dm * NSAMP + n0 + s]       = om;
                        g_tmp[(size_t)(dm + 2) * NSAMP + n0 + s] = op;
                    }
                }
            }
        }
    } else if (w < 12) {
        // m0: warp w-8, outs [48(w-8), 48(w-8)+48), bias. K=192, O=192.
        const float* Wh = g_W0h + b * 36864;
        const float* Wl = g_W0l + b * 36864;
        int ow = 48 * (w - 8);
        #pragma unroll 1
        for (int pass = 0; pass < 2; pass++) {
            int o_base = ow + 24 * pass;
            float acc[3][4][4];  // [n][m][c]
            #pragma unroll
            for (int nn = 0; nn < 3; nn++) {
                float bv0 = g_bc0[b * 192 + o_base + 8 * nn + 2 * t];
                float bv1 = g_bc0[b * 192 + o_base + 8 * nn + 2 * t + 1];
                #pragma unroll
                for (int m = 0; m < 4; m++) {
                    acc[nn][m][0] = bv0; acc[nn][m][1] = bv1;
                    acc[nn][m][2] = bv0; acc[nn][m][3] = bv1;
                }
            }
            #pragma unroll 1
            for (int k0 = 0; k0 < 192; k0 += 8) {
                uint32_t Bh[3][2], Bl[3][2];
                #pragma unroll
                for (int nn = 0; nn < 3; nn++)
                    load_b_frag(Wh, Wl, 192, k0, o_base + 8 * nn, g, t, Bh[nn], Bl[nn]);
                #pragma unroll
                for (int m = 0; m < 4; m++) {
                    uint32_t Ah[4], Al[4];
                    load_a_frag(A, 16 * m, 0, k0, g, t, Ah, Al);
                    #pragma unroll
                    for (int nn = 0; nn < 3; nn++)
                        mma3x(acc[nn][m], Ah, Al, Bh[nn], Bl[nn]);
                }
            }
            #pragma unroll
            for (int nn = 0; nn < 3; nn++)
                #pragma unroll
                for (int m = 0; m < 4; m++)
                    #pragma unroll
                    for (int c = 0; c < 4; c++) {
                        int o = o_base + 8 * nn + 2 * t + (c & 1);
                        int s = 16 * m + g + ((c >> 1) ? 8 : 0);
                        int dim = (o < 64) ? o : (o < 128) ? (3 * o - 127) : (5 * o - 382);
                        g_tmp[(size_t)dim * NSAMP + n0 + s] = acc[nn][m][c];
                    }
        }
    } else {
        // m2: warp w-12, real outs [16(w-12), +16), imag +64. K=64, O=128.
        const float* Wh = g_W2h + b * 8192;
        const float* Wl = g_W2l + b * 8192;
        int orb = 16 * (w - 12);
        int on[4] = { orb, orb + 8, 64 + orb, 72 + orb };
        #pragma unroll 1
        for (int tt = 0; tt < 2; tt++) {
            float acc[2][2][4][4];
            #pragma unroll
            for (int jj = 0; jj < 2; jj++)
                #pragma unroll
                for (int pp = 0; pp < 2; pp++)
                    #pragma unroll
                    for (int nn = 0; nn < 4; nn++)
                        #pragma unroll
                        for (int c = 0; c < 4; c++) acc[jj][pp][nn][c] = 0.f;
            #pragma unroll 1
            for (int k0 = 0; k0 < 64; k0 += 8) {
                uint32_t Bh[4][2], Bl[4][2];
                #pragma unroll
                for (int nn = 0; nn < 4; nn++)
                    load_b_frag(Wh, Wl, 128, k0, on[nn], g, t, Bh[nn], Bl[nn]);
                #pragma unroll
                for (int jj = 0; jj < 2; jj++) {
                    int mrow0 = 16 * (2 * tt + jj);
                    #pragma unroll
                    for (int pp = 0; pp < 2; pp++) {
                        uint32_t Ah[4], Al[4];
                        load_a_frag(A, mrow0, pp ? 512 : 448, k0, g, t, Ah, Al);
                        #pragma unroll
                        for (int nn = 0; nn < 4; nn++)
                            mma3x(acc[jj][pp][nn], Ah, Al, Bh[nn], Bl[nn]);
                    }
                }
            }
            #pragma unroll
            for (int jj = 0; jj < 2; jj++) {
                int sbase = 16 * (2 * tt + jj);
                #pragma unroll
                for (int nr = 0; nr < 2; nr++) {
                    #pragma unroll
                    for (int c = 0; c < 4; c++) {
                        int k = orb + 8 * nr + 2 * t + (c & 1);
                        int s = sbase + g + ((c >> 1) ? 8 : 0);
                        float om = acc[jj][0][nr][c]     - acc[jj][1][2 + nr][c];
                        float op = acc[jj][1][nr][c]     + acc[jj][0][2 + nr][c];
                        int dm = 256 + 5 * k;
                        g_tmp[(size_t)dm * NSAMP + n0 + s]       = om;
                        g_tmp[(size_t)(dm + 4) * NSAMP + n0 + s] = op;
                    }
                }
            }
        }
    }
}

// Kernel 2: back-rotation (unchanged).
#define K2THR 256
#define SM2_S   0
#define SM2_D1B (576 * 33)
#define SM2_D2B (SM2_D1B + 32 * 9)
#define SM2_TOT (SM2_D2B + 32 * 25)

__global__ __launch_bounds__(K2THR, 1)
void so2_backrot_kernel(const float* __restrict__ alpha,
                        const float* __restrict__ beta,
                        const float* __restrict__ gamma_,
                        const float* __restrict__ Jd1,
                        const float* __restrict__ Jd2,
                        float* __restrict__ out)
{
    extern __shared__ float sm[];
    float* S   = sm + SM2_S;
    float* D1b = sm + SM2_D1B;
    float* D2b = sm + SM2_D2B;

    const int tid  = threadIdx.x;
    const int w    = tid >> 5;
    const int lane = tid & 31;
    const int n0   = blockIdx.x * 32;

    for (int idx = tid; idx < 576 * 32; idx += K2THR) {
        int d = idx >> 5, s = idx & 31;
        S[d * 33 + s] = g_tmp[(size_t)d * NSAMP + n0 + s];
    }
    if (tid < 32) {
        int n = n0 + tid;
        build_D(-gamma_[n], -beta[n], -alpha[n], Jd1, Jd2,
                D1b + tid * 9, D2b + tid * 25);
    }
    __syncthreads();

    {
        float e1[9], e2[25];
        #pragma unroll
        for (int j = 0; j < 9; j++)  e1[j] = D1b[lane * 9 + j];
        #pragma unroll
        for (int j = 0; j < 25; j++) e2[j] = D2b[lane * 25 + j];
        #pragma unroll
        for (int k = 0; k < 8; k++) {
            int c = w + 8 * k;
            float v0 = S[(64 + 3 * c) * 33 + lane];
            float v1 = S[(64 + 3 * c + 1) * 33 + lane];
            float v2 = S[(64 + 3 * c + 2) * 33 + lane];
            S[(64 + 3 * c) * 33 + lane]     = fmaf(e1[0], v0, fmaf(e1[1], v1, e1[2] * v2));
            S[(64 + 3 * c + 1) * 33 + lane] = fmaf(e1[3], v0, fmaf(e1[4], v1, e1[5] * v2));
            S[(64 + 3 * c + 2) * 33 + lane] = fmaf(e1[6], v0, fmaf(e1[7], v1, e1[8] * v2));
            float u0 = S[(256 + 5 * c) * 33 + lane];
            float u1 = S[(256 + 5 * c + 1) * 33 + lane];
            float u2 = S[(256 + 5 * c + 2) * 33 + lane];
            float u3 = S[(256 + 5 * c + 3) * 33 + lane];
            float u4 = S[(256 + 5 * c + 4) * 33 + lane];
            #pragma unroll
            for (int i = 0; i < 5; i++)
                S[(256 + 5 * c + i) * 33 + lane] =
                    fmaf(e2[i*5+0], u0, fmaf(e2[i*5+1], u1, fmaf(e2[i*5+2], u2,
                    fmaf(e2[i*5+3], u3, e2[i*5+4] * u4))));
        }
    }
    __syncthreads();

    for (int idx = tid; idx < 32 * 576; idx += K2THR) {
        int s = idx / 576, d = idx % 576;
        out[(size_t)(n0 + s) * 576 + d] = S[d * 33 + s];
    }
}

extern "C" void kernel_launch(void* const* d_in, const int* in_sizes, int n_in,
                              void* d_out, int out_size)
{
    const float* x     = (const float*)d_in[0];
    const float* alpha = (const float*)d_in[1];
    const float* beta  = (const float*)d_in[2];
    const float* gamma_= (const float*)d_in[3];
    const float* coef  = (const float*)d_in[4];
    const float* Jd1   = (const float*)d_in[5];
    const float* Jd2   = (const float*)d_in[6];
    const float* w0    = (const float*)d_in[7];
    const float* b0    = (const float*)d_in[8];
    const float* ws0   = (const float*)d_in[9];
    const float* bs0   = (const float*)d_in[10];
    const float* w1    = (const float*)d_in[11];
    const float* ws1   = (const float*)d_in[12];
    const float* w2    = (const float*)d_in[13];
    const float* ws2   = (const float*)d_in[14];
    float* out = (float*)d_out;

    const int totalW = 8 * 192 * 192 + 8 * 192 + 8 * 128 * 256 + 8 * 64 * 128;
    prep_weights_kernel<<<(totalW + 255) / 256, 256>>>(coef, w0, b0, ws0, bs0,
                                                       w1, ws1, w2, ws2);

    const int smem1 = SM1_TOT * sizeof(float);
    cudaFuncSetAttribute(so2_gemm_kernel,
                         cudaFuncAttributeMaxDynamicSharedMemorySize, smem1);
    so2_gemm_kernel<<<NSAMP / TILE, NTHR, smem1>>>(x, alpha, beta, gamma_, Jd1, Jd2);

    const int smem2 = SM2_TOT * sizeof(float);
    cudaFuncSetAttribute(so2_backrot_kernel,
                         cudaFuncAttributeMaxDynamicSharedMemorySize, smem2);
    so2_backrot_kernel<<<NSAMP / 32, K2THR, smem2>>>(alpha, beta, gamma_,
                                                     Jd1, Jd2, out);
}

// round 15
// speedup vs baseline: 2.3170x; 1.2589x over previous
#include <cuda_runtime.h>
#include <math.h>
#include <stdint.h>

#define NSAMP 64000
#define TILE  64
#define NTHR  512
#define SPB   8000

// Packed bf16x2 hi/lo weight planes, [b][k2][o] (k2 = k/2; low half = even k)
__device__ __align__(16) uint32_t g_W0h[8 * 96 * 192];
__device__ __align__(16) uint32_t g_W0l[8 * 96 * 192];
__device__ __align__(16) uint32_t g_W1h[8 * 64 * 256];
__device__ __align__(16) uint32_t g_W1l[8 * 64 * 256];
__device__ __align__(16) uint32_t g_W2h[8 * 32 * 128];
__device__ __align__(16) uint32_t g_W2l[8 * 32 * 128];
__device__ __align__(16) float    g_bc0[8 * 192];
__device__ float g_tmp[576 * NSAMP];

__device__ __forceinline__ unsigned short bf16h(float v) {
    unsigned short u; asm("cvt.rn.bf16.f32 %0, %1;" : "=h"(u) : "f"(v)); return u;
}
__device__ __forceinline__ float bf16f(unsigned short u) {
    return __uint_as_float((uint32_t)u << 16);
}
// split (v0,v1) -> packed hi / packed lo (low half = v0)
__device__ __forceinline__ void split_pack(float v0, float v1,
                                           uint32_t& hi, uint32_t& lo) {
    unsigned short h0 = bf16h(v0), h1 = bf16h(v1);
    unsigned short l0 = bf16h(v0 - bf16f(h0)), l1 = bf16h(v1 - bf16f(h1));
    hi = (uint32_t)h0 | ((uint32_t)h1 << 16);
    lo = (uint32_t)l0 | ((uint32_t)l1 << 16);
}

__device__ __forceinline__ void mma16(float* d, const uint32_t* a, const uint32_t* b) {
    asm("mma.sync.aligned.m16n8k16.row.col.f32.bf16.bf16.f32 "
        "{%0,%1,%2,%3},{%4,%5,%6,%7},{%8,%9},{%0,%1,%2,%3};"
        : "+f"(d[0]), "+f"(d[1]), "+f"(d[2]), "+f"(d[3])
        : "r"(a[0]), "r"(a[1]), "r"(a[2]), "r"(a[3]), "r"(b[0]), "r"(b[1]));
}
__device__ __forceinline__ void mma3x(float* d, const uint32_t* ah, const uint32_t* al,
                                      const uint32_t* bh, const uint32_t* bl) {
    mma16(d, ah, bh);
    mma16(d, ah, bl);
    mma16(d, al, bh);
}

// prep: thread handles one (b, k2, o): expert-mix two k values, split+pack.
__global__ void prep_weights_kernel(
    const float* __restrict__ coef,
    const float* __restrict__ w0, const float* __restrict__ b0,
    const float* __restrict__ ws0, const float* __restrict__ bs0,
    const float* __restrict__ w1, const float* __restrict__ ws1,
    const float* __restrict__ w2, const float* __restrict__ ws2)
{
    int idx = blockIdx.x * blockDim.x + threadIdx.x;
    const int S0 = 8 * 96 * 192;
    const int S1 = 8 * 192;
    const int S2 = 8 * 64 * 256;
    const int S3 = 8 * 32 * 128;
    if (idx < S0) {
        int b = idx / (96 * 192), r = idx % (96 * 192);
        int k2 = r / 192, o = r % 192;
        float v0 = ws0[o * 192 + 2 * k2];
        float v1 = ws0[o * 192 + 2 * k2 + 1];
        #pragma unroll
        for (int e = 0; e < 8; e++) {
            float ce = coef[b * 8 + e];
            v0 = fmaf(ce, w0[e * 36864 + o * 192 + 2 * k2],     v0);
            v1 = fmaf(ce, w0[e * 36864 + o * 192 + 2 * k2 + 1], v1);
        }
        uint32_t hi, lo; split_pack(v0, v1, hi, lo);
        g_W0h[b * 96 * 192 + k2 * 192 + o] = hi;
        g_W0l[b * 96 * 192 + k2 * 192 + o] = lo;
        return;
    }
    idx -= S0;
    if (idx < S1) {
        int b = idx / 192, o = idx % 192;
        float v = bs0[o];
        #pragma unroll
        for (int e = 0; e < 8; e++)
            v = fmaf(coef[b * 8 + e], b0[e * 192 + o], v);
        g_bc0[b * 192 + o] = v;
        return;
    }
    idx -= S1;
    if (idx < S2) {
        int b = idx / (64 * 256), r = idx % (64 * 256);
        int k2 = r / 256, o = r % 256;
        float v0 = ws1[o * 128 + 2 * k2];
        float v1 = ws1[o * 128 + 2 * k2 + 1];
        #pragma unroll
        for (int e = 0; e < 8; e++) {
            float ce = coef[b * 8 + e];
            v0 = fmaf(ce, w1[e * 32768 + o * 128 + 2 * k2],     v0);
            v1 = fmaf(ce, w1[e * 32768 + o * 128 + 2 * k2 + 1], v1);
        }
        uint32_t hi, lo; split_pack(v0, v1, hi, lo);
        g_W1h[b * 64 * 256 + k2 * 256 + o] = hi;
        g_W1l[b * 64 * 256 + k2 * 256 + o] = lo;
        return;
    }
    idx -= S2;
    if (idx < S3) {
        int b = idx / (32 * 128), r = idx % (32 * 128);
        int k2 = r / 128, o = r % 128;
        float v0 = ws2[o * 64 + 2 * k2];
        float v1 = ws2[o * 64 + 2 * k2 + 1];
        #pragma unroll
        for (int e = 0; e < 8; e++) {
            float ce = coef[b * 8 + e];
            v0 = fmaf(ce, w2[e * 8192 + o * 64 + 2 * k2],     v0);
            v1 = fmaf(ce, w2[e * 8192 + o * 64 + 2 * k2 + 1], v1);
        }
        uint32_t hi, lo; split_pack(v0, v1, hi, lo);
        g_W2h[b * 32 * 128 + k2 * 128 + o] = hi;
        g_W2l[b * 32 * 128 + k2 * 128 + o] = lo;
    }
}

__device__ __forceinline__ void mm3(const float* P, const float* Q, float* R) {
    #pragma unroll
    for (int i = 0; i < 3; i++)
        #pragma unroll
        for (int j = 0; j < 3; j++) {
            float acc = 0.f;
            #pragma unroll
            for (int k = 0; k < 3; k++) acc = fmaf(P[i * 3 + k], Q[k * 3 + j], acc);
            R[i * 3 + j] = acc;
        }
}
__device__ __forceinline__ void mm5(const float* P, const float* Q, float* R) {
    #pragma unroll
    for (int i = 0; i < 5; i++)
        #pragma unroll
        for (int j = 0; j < 5; j++) {
            float acc = 0.f;
            #pragma unroll
            for (int k = 0; k < 5; k++) acc = fmaf(P[i * 5 + k], Q[k * 5 + j], acc);
            R[i * 5 + j] = acc;
        }
}

__device__ void build_D(float a1, float a2, float a3,
                        const float* __restrict__ J1g,
                        const float* __restrict__ J2g,
                        float* __restrict__ D1, float* __restrict__ D2)
{
    float J1[9], J2[25];
    #pragma unroll
    for (int i = 0; i < 9; i++) J1[i] = J1g[i];
    #pragma unroll
    for (int i = 0; i < 25; i++) J2[i] = J2g[i];

    float X[3][9], Y[3][25];
    float aa[3] = {a1, a2, a3};
    #pragma unroll
    for (int t = 0; t < 3; t++) {
        float c1, s1, c2, s2;
        sincosf(aa[t], &s1, &c1);
        sincosf(2.0f * aa[t], &s2, &c2);
        float* Xp = X[t];
        Xp[0] = c1;  Xp[1] = 0.f; Xp[2] = s1;
        Xp[3] = 0.f; Xp[4] = 1.f; Xp[5] = 0.f;
        Xp[6] = -s1; Xp[7] = 0.f; Xp[8] = c1;
        float* Yp = Y[t];
        #pragma unroll
        for (int q = 0; q < 25; q++) Yp[q] = 0.f;
        Yp[0]  = c2;  Yp[4]  = s2;
        Yp[6]  = c1;  Yp[8]  = s1;
        Yp[12] = 1.f;
        Yp[16] = -s1; Yp[18] = c1;
        Yp[20] = -s2; Yp[24] = c2;
    }
    float T1[9], T2[9];
    mm3(X[0], J1, T1);
    mm3(T1, X[1], T2);
    mm3(T2, J1, T1);
    mm3(T1, X[2], D1);
    float U1[25], U2[25];
    mm5(Y[0], J2, U1);
    mm5(U1, Y[1], U2);
    mm5(U2, J2, U1);
    mm5(U1, Y[2], D2);
}

// Kernel 1 SMEM (uint32 words):
//   AH [64*292], AL [64*292]  packed bf16x2 planes, [sample][k2], stride 292
//   ST [16*577] fp32 staging; D1f [64*9], D2f [64*25] fp32
#define ASTR2   292
#define SM_AH   0
#define SM_AL   (64 * ASTR2)
#define SM_ST   (2 * 64 * ASTR2)
#define SM_D1F  (SM_ST + 16 * 577)
#define SM_D2F  (SM_D1F + 64 * 9)
#define SM1_TOT (SM_D2F + 64 * 25)

__device__ __forceinline__ void load_a_frag(const uint32_t* __restrict__ P,
                                            int mrow0, int k2base, int k2_0,
                                            int g, int t, uint32_t* a)
{
    const uint32_t* p = P + (mrow0 + g) * ASTR2 + k2base + k2_0;
    a[0] = p[t];
    a[1] = p[8 * ASTR2 + t];
    a[2] = p[t + 4];
    a[3] = p[8 * ASTR2 + t + 4];
}
__device__ __forceinline__ void load_b_frag(const uint32_t* __restrict__ W,
                                            int ldo, int k2_0, int o0,
                                            int g, int t, uint32_t* b)
{
    const uint32_t* p = W + (k2_0 + t) * ldo + o0 + g;
    b[0] = p[0];
    b[1] = p[4 * ldo];
}

__global__ __launch_bounds__(NTHR, 1)
void so2_gemm_kernel(const float* __restrict__ x,
                     const float* __restrict__ alpha,
                     const float* __restrict__ beta,
                     const float* __restrict__ gamma_,
                     const float* __restrict__ Jd1,
                     const float* __restrict__ Jd2)
{
    extern __shared__ uint32_t smw[];
    uint32_t* AH = smw + SM_AH;
    uint32_t* AL = smw + SM_AL;
    float* ST  = (float*)(smw + SM_ST);
    float* D1f = (float*)(smw + SM_D1F);
    float* D2f = (float*)(smw + SM_D2F);

    const int tid  = threadIdx.x;
    const int w    = tid >> 5;
    const int lane = tid & 31;
    const int g    = lane >> 2;
    const int t    = lane & 3;
    const int n0   = blockIdx.x * TILE;
    const int b    = n0 / SPB;
    const float* xg = x + (size_t)n0 * 576;

    // ---- Phase 1: fwd Wigner (threads 0-63) + stage pass 0 ----
    if (tid < 64) {
        int n = n0 + tid;
        build_D(alpha[n], beta[n], gamma_[n], Jd1, Jd2,
                D1f + tid * 9, D2f + tid * 25);
    } else {
        for (int idx = tid - 64; idx < 16 * 576; idx += NTHR - 64) {
            int s = idx / 576, d = idx % 576;
            ST[s * 577 + d] = xg[idx];
        }
    }
    __syncthreads();

    // ---- 4 passes: rotate 16 samples, each thread = one channel-PAIR ----
    for (int p = 0; p < 4; p++) {
        {
            int s16 = tid & 15;
            int grp = tid >> 4;   // 0..31: channel pair (2grp, 2grp+1)
            int s   = p * 16 + s16;
            const float* br = ST + s16 * 577;
            uint32_t* AHs = AH + s * ASTR2;
            uint32_t* ALs = AL + s * ASTR2;
            float d1[9], d2[25];
            #pragma unroll
            for (int j = 0; j < 9; j++)  d1[j] = D1f[s * 9 + j];
            #pragma unroll
            for (int j = 0; j < 25; j++) d2[j] = D2f[s * 25 + j];

            // l=0
            {
                uint32_t hi, lo;
                split_pack(br[2 * grp], br[2 * grp + 1], hi, lo);
                AHs[grp] = hi; ALs[grp] = lo;
            }
            // l=1, l=2 for both channels of the pair
            float y0[2], y1[2], y2[2], rr[5][2];
            #pragma unroll
            for (int cc = 0; cc < 2; cc++) {
                int c = 2 * grp + cc;
                float v0 = br[64 + 3 * c], v1 = br[64 + 3 * c + 1], v2 = br[64 + 3 * c + 2];
                y0[cc] = fmaf(d1[0], v0, fmaf(d1[1], v1, d1[2] * v2));  // dim 192+c
                y1[cc] = fmaf(d1[3], v0, fmaf(d1[4], v1, d1[5] * v2));  // dim 64+c
                y2[cc] = fmaf(d1[6], v0, fmaf(d1[7], v1, d1[8] * v2));  // dim 320+c
                float u0 = br[256 + 5 * c],     u1 = br[256 + 5 * c + 1], u2 = br[256 + 5 * c + 2];
                float u3 = br[256 + 5 * c + 3], u4 = br[256 + 5 * c + 4];
                #pragma unroll
                for (int i = 0; i < 5; i++)
                    rr[i][cc] = fmaf(d2[i*5+0], u0, fmaf(d2[i*5+1], u1, fmaf(d2[i*5+2], u2,
                                fmaf(d2[i*5+3], u3, d2[i*5+4] * u4))));
            }
            uint32_t hi, lo;
            split_pack(y0[0], y0[1], hi, lo); AHs[96 + grp]  = hi; ALs[96 + grp]  = lo;
            split_pack(y1[0], y1[1], hi, lo); AHs[32 + grp]  = hi; ALs[32 + grp]  = lo;
            split_pack(y2[0], y2[1], hi, lo); AHs[160 + grp] = hi; ALs[160 + grp] = lo;
            split_pack(rr[0][0], rr[0][1], hi, lo); AHs[224 + grp] = hi; ALs[224 + grp] = lo;
            split_pack(rr[1][0], rr[1][1], hi, lo); AHs[128 + grp] = hi; ALs[128 + grp] = lo;
            split_pack(rr[2][0], rr[2][1], hi, lo); AHs[64 + grp]  = hi; ALs[64 + grp]  = lo;
            split_pack(rr[3][0], rr[3][1], hi, lo); AHs[192 + grp] = hi; ALs[192 + grp] = lo;
            split_pack(rr[4][0], rr[4][1], hi, lo); AHs[256 + grp] = hi; ALs[256 + grp] = lo;
        }
        __syncthreads();
        if (p < 3) {
            const float* xp = xg + (p + 1) * 16 * 576;
            for (int idx = tid; idx < 16 * 576; idx += NTHR) {
                int s = idx / 576, d = idx % 576;
                ST[s * 577 + d] = xp[idx];
            }
            __syncthreads();
        }
    }

    // ---- Phase 2: 3xBF16 tensor-core GEMMs (m16n8k16) ----
    if (w < 8) {
        // m1: K=128 (8 k16 steps), x0 k2base 96, x1 k2base 160.
        const uint32_t* Wh = g_W1h + b * 64 * 256;
        const uint32_t* Wl = g_W1l + b * 64 * 256;
        int orb = 16 * w;
        int on[4] = { orb, orb + 8, 128 + orb, 136 + orb };  // r0 r1 i0 i1
        #pragma unroll 1
        for (int tt = 0; tt < 2; tt++) {
            float acc[2][2][4][4];
            #pragma unroll
            for (int jj = 0; jj < 2; jj++)
                #pragma unroll
                for (int pp = 0; pp < 2; pp++)
                    #pragma unroll
                    for (int nn = 0; nn < 4; nn++)
                        #pragma unroll
                        for (int c = 0; c < 4; c++) acc[jj][pp][nn][c] = 0.f;
            #pragma unroll 1
            for (int k2_0 = 0; k2_0 < 64; k2_0 += 8) {
                uint32_t Bh[4][2], Bl[4][2];
                #pragma unroll
                for (int nn = 0; nn < 4; nn++) {
                    load_b_frag(Wh, 256, k2_0, on[nn], g, t, Bh[nn]);
                    load_b_frag(Wl, 256, k2_0, on[nn], g, t, Bl[nn]);
                }
                #pragma unroll
                for (int jj = 0; jj < 2; jj++) {
                    int mrow0 = 16 * (2 * tt + jj);
                    #pragma unroll
                    for (int pp = 0; pp < 2; pp++) {
                        uint32_t Ah[4], Al[4];
                        load_a_frag(AH, mrow0, pp ? 160 : 96, k2_0, g, t, Ah);
                        load_a_frag(AL, mrow0, pp ? 160 : 96, k2_0, g, t, Al);
                        #pragma unroll
                        for (int nn = 0; nn < 4; nn++)
                            mma3x(acc[jj][pp][nn], Ah, Al, Bh[nn], Bl[nn]);
                    }
                }
            }
            #pragma unroll
            for (int jj = 0; jj < 2; jj++) {
                int sbase = 16 * (2 * tt + jj);
                #pragma unroll
                for (int nr = 0; nr < 2; nr++) {
                    #pragma unroll
                    for (int c = 0; c < 4; c++) {
                        int k = orb + 8 * nr + 2 * t + (c & 1);
                        int s = sbase + g + ((c >> 1) ? 8 : 0);
                        float om = acc[jj][0][nr][c]     - acc[jj][1][2 + nr][c];
                        float op = acc[jj][1][nr][c]     + acc[jj][0][2 + nr][c];
                        int dm = (k < 64) ? (64 + 3 * k) : (256 + 5 * (k - 64) + 1);
                        g_tmp[(size_t)dm * NSAMP + n0 + s]       = om;
                        g_tmp[(size_t)(dm + 2) * NSAMP + n0 + s] = op;
                    }
                }
            }
        }
    } else if (w < 12) {
        // m0: K=192 (12 k16 steps), k2base 0.
        const uint32_t* Wh = g_W0h + b * 96 * 192;
        const uint32_t* Wl = g_W0l + b * 96 * 192;
        int ow = 48 * (w - 8);
        #pragma unroll 1
        for (int pass = 0; pass < 2; pass++) {
            int o_base = ow + 24 * pass;
            float acc[3][4][4];
            #pragma unroll
            for (int nn = 0; nn < 3; nn++) {
                float bv0 = g_bc0[b * 192 + o_base + 8 * nn + 2 * t];
                float bv1 = g_bc0[b * 192 + o_base + 8 * nn + 2 * t + 1];
                #pragma unroll
                for (int m = 0; m < 4; m++) {
                    acc[nn][m][0] = bv0; acc[nn][m][1] = bv1;
                    acc[nn][m][2] = bv0; acc[nn][m][3] = bv1;
                }
            }
            #pragma unroll 1
            for (int k2_0 = 0; k2_0 < 96; k2_0 += 8) {
                uint32_t Bh[3][2], Bl[3][2];
                #pragma unroll
                for (int nn = 0; nn < 3; nn++) {
                    load_b_frag(Wh, 192, k2_0, o_base + 8 * nn, g, t, Bh[nn]);
                    load_b_frag(Wl, 192, k2_0, o_base + 8 * nn, g, t, Bl[nn]);
                }
                #pragma unroll
                for (int m = 0; m < 4; m++) {
                    uint32_t Ah[4], Al[4];
                    load_a_frag(AH, 16 * m, 0, k2_0, g, t, Ah);
                    load_a_frag(AL, 16 * m, 0, k2_0, g, t, Al);
                    #pragma unroll
                    for (int nn = 0; nn < 3; nn++)
                        mma3x(acc[nn][m], Ah, Al, Bh[nn], Bl[nn]);
                }
            }
            #pragma unroll
            for (int nn = 0; nn < 3; nn++)
                #pragma unroll
                for (int m = 0; m < 4; m++)
                    #pragma unroll
                    for (int c = 0; c < 4; c++) {
                        int o = o_base + 8 * nn + 2 * t + (c & 1);
                        int s = 16 * m + g + ((c >> 1) ? 8 : 0);
                        int dim = (o < 64) ? o : (o < 128) ? (3 * o - 127) : (5 * o - 382);
                        g_tmp[(size_t)dim * NSAMP + n0 + s] = acc[nn][m][c];
                    }
        }
    } else {
        // m2: K=64 (4 k16 steps), x0 k2base 224, x1 k2base 256.
        const uint32_t* Wh = g_W2h + b * 32 * 128;
        const uint32_t* Wl = g_W2l + b * 32 * 128;
        int orb = 16 * (w - 12);
        int on[4] = { orb, orb + 8, 64 + orb, 72 + orb };
        #pragma unroll 1
        for (int tt = 0; tt < 2; tt++) {
            float acc[2][2][4][4];
            #pragma unroll
            for (int jj = 0; jj < 2; jj++)
                #pragma unroll
                for (int pp = 0; pp < 2; pp++)
                    #pragma unroll
                    for (int nn = 0; nn < 4; nn++)
                        #pragma unroll
                        for (int c = 0; c < 4; c++) acc[jj][pp][nn][c] = 0.f;
            #pragma unroll 1
            for (int k2_0 = 0; k2_0 < 32; k2_0 += 8) {
                uint32_t Bh[4][2], Bl[4][2];
                #pragma unroll
                for (int nn = 0; nn < 4; nn++) {
                    load_b_frag(Wh, 128, k2_0, on[nn], g, t, Bh[nn]);
                    load_b_frag(Wl, 128, k2_0, on[nn], g, t, Bl[nn]);
                }
                #pragma unroll
                for (int jj = 0; jj < 2; jj++) {
                    int mrow0 = 16 * (2 * tt + jj);
                    #pragma unroll
                    for (int pp = 0; pp < 2; pp++) {
                        uint32_t Ah[4], Al[4];
                        load_a_frag(AH, mrow0, pp ? 256 : 224, k2_0, g, t, Ah);
                        load_a_frag(AL, mrow0, pp ? 256 : 224, k2_0, g, t, Al);
                        #pragma unroll
                        for (int nn = 0; nn < 4; nn++)
                            mma3x(acc[jj][pp][nn], Ah, Al, Bh[nn], Bl[nn]);
                    }
                }
            }
            #pragma unroll
            for (int jj = 0; jj < 2; jj++) {
                int sbase = 16 * (2 * tt + jj);
                #pragma unroll
                for (int nr = 0; nr < 2; nr++) {
                    #pragma unroll
                    for (int c = 0; c < 4; c++) {
                        int k = orb + 8 * nr + 2 * t + (c & 1);
                        int s = sbase + g + ((c >> 1) ? 8 : 0);
                        float om = acc[jj][0][nr][c]     - acc[jj][1][2 + nr][c];
                        float op = acc[jj][1][nr][c]     + acc[jj][0][2 + nr][c];
                        int dm = 256 + 5 * k;
                        g_tmp[(size_t)dm * NSAMP + n0 + s]       = om;
                        g_tmp[(size_t)(dm + 4) * NSAMP + n0 + s] = op;
                    }
                }
            }
        }
    }
}

// Kernel 2: back-rotation (unchanged).
#define K2THR 256
#define SM2_S   0
#define SM2_D1B (576 * 33)
#define SM2_D2B (SM2_D1B + 32 * 9)
#define SM2_TOT (SM2_D2B + 32 * 25)

__global__ __launch_bounds__(K2THR, 1)
void so2_backrot_kernel(const float* __restrict__ alpha,
                        const float* __restrict__ beta,
                        const float* __restrict__ gamma_,
                        const float* __restrict__ Jd1,
                        const float* __restrict__ Jd2,
                        float* __restrict__ out)
{
    extern __shared__ float sm[];
    float* S   = sm + SM2_S;
    float* D1b = sm + SM2_D1B;
    float* D2b = sm + SM2_D2B;

    const int tid  = threadIdx.x;
    const int w    = tid >> 5;
    const int lane = tid & 31;
    const int n0   = blockIdx.x * 32;

    for (int idx = tid; idx < 576 * 32; idx += K2THR) {
        int d = idx >> 5, s = idx & 31;
        S[d * 33 + s] = g_tmp[(size_t)d * NSAMP + n0 + s];
    }
    if (tid < 32) {
        int n = n0 + tid;
        build_D(-gamma_[n], -beta[n], -alpha[n], Jd1, Jd2,
                D1b + tid * 9, D2b + tid * 25);
    }
    __syncthreads();

    {
        float e1[9], e2[25];
        #pragma unroll
        for (int j = 0; j < 9; j++)  e1[j] = D1b[lane * 9 + j];
        #pragma unroll
        for (int j = 0; j < 25; j++) e2[j] = D2b[lane * 25 + j];
        #pragma unroll
        for (int k = 0; k < 8; k++) {
            int c = w + 8 * k;
            float v0 = S[(64 + 3 * c) * 33 + lane];
            float v1 = S[(64 + 3 * c + 1) * 33 + lane];
            float v2 = S[(64 + 3 * c + 2) * 33 + lane];
            S[(64 + 3 * c) * 33 + lane]     = fmaf(e1[0], v0, fmaf(e1[1], v1, e1[2] * v2));
            S[(64 + 3 * c + 1) * 33 + lane] = fmaf(e1[3], v0, fmaf(e1[4], v1, e1[5] * v2));
            S[(64 + 3 * c + 2) * 33 + lane] = fmaf(e1[6], v0, fmaf(e1[7], v1, e1[8] * v2));
            float u0 = S[(256 + 5 * c) * 33 + lane];
            float u1 = S[(256 + 5 * c + 1) * 33 + lane];
            float u2 = S[(256 + 5 * c + 2) * 33 + lane];
            float u3 = S[(256 + 5 * c + 3) * 33 + lane];
            float u4 = S[(256 + 5 * c + 4) * 33 + lane];
            #pragma unroll
            for (int i = 0; i < 5; i++)
                S[(256 + 5 * c + i) * 33 + lane] =
                    fmaf(e2[i*5+0], u0, fmaf(e2[i*5+1], u1, fmaf(e2[i*5+2], u2,
                    fmaf(e2[i*5+3], u3, e2[i*5+4] * u4))));
        }
    }
    __syncthreads();

    for (int idx = tid; idx < 32 * 576; idx += K2THR) {
        int s = idx / 576, d = idx % 576;
        out[(size_t)(n0 + s) * 576 + d] = S[d * 33 + s];
    }
}

extern "C" void kernel_launch(void* const* d_in, const int* in_sizes, int n_in,
                              void* d_out, int out_size)
{
    const float* x     = (const float*)d_in[0];
    const float* alpha = (const float*)d_in[1];
    const float* beta  = (const float*)d_in[2];
    const float* gamma_= (const float*)d_in[3];
    const float* coef  = (const float*)d_in[4];
    const float* Jd1   = (const float*)d_in[5];
    const float* Jd2   = (const float*)d_in[6];
    const float* w0    = (const float*)d_in[7];
    const float* b0    = (const float*)d_in[8];
    const float* ws0   = (const float*)d_in[9];
    const float* bs0   = (const float*)d_in[10];
    const float* w1    = (const float*)d_in[11];
    const float* ws1   = (const float*)d_in[12];
    const float* w2    = (const float*)d_in[13];
    const float* ws2   = (const float*)d_in[14];
    float* out = (float*)d_out;

    const int totalW = 8 * 96 * 192 + 8 * 192 + 8 * 64 * 256 + 8 * 32 * 128;
    prep_weights_kernel<<<(totalW + 255) / 256, 256>>>(coef, w0, b0, ws0, bs0,
                                                       w1, ws1, w2, ws2);

    const int smem1 = SM1_TOT * sizeof(uint32_t);
    cudaFuncSetAttribute(so2_gemm_kernel,
                         cudaFuncAttributeMaxDynamicSharedMemorySize, smem1);
    so2_gemm_kernel<<<NSAMP / TILE, NTHR, smem1>>>(x, alpha, beta, gamma_, Jd1, Jd2);

    const int smem2 = SM2_TOT * sizeof(float);
    cudaFuncSetAttribute(so2_backrot_kernel,
                         cudaFuncAttributeMaxDynamicSharedMemorySize, smem2);
    so2_backrot_kernel<<<NSAMP / 32, K2THR, smem2>>>(alpha, beta, gamma_,
                                                     Jd1, Jd2, out);
}

// round 16
// speedup vs baseline: 2.3582x; 1.0178x over previous
#include <cuda_runtime.h>
#include <math.h>
#include <stdint.h>

#define NSAMP 64000
#define TILE  64
#define NTHR  512
#define SPB   8000

// Packed bf16x2 hi/lo weight planes, [b][k2][o] (k2 = k/2; low half = even k)
__device__ __align__(16) uint32_t g_W0h[8 * 96 * 192];
__device__ __align__(16) uint32_t g_W0l[8 * 96 * 192];
__device__ __align__(16) uint32_t g_W1h[8 * 64 * 256];
__device__ __align__(16) uint32_t g_W1l[8 * 64 * 256];
__device__ __align__(16) uint32_t g_W2h[8 * 32 * 128];
__device__ __align__(16) uint32_t g_W2l[8 * 32 * 128];
__device__ __align__(16) float    g_bc0[8 * 192];
__device__ float g_tmp[576 * NSAMP];

__device__ __forceinline__ unsigned short bf16h(float v) {
    unsigned short u; asm("cvt.rn.bf16.f32 %0, %1;" : "=h"(u) : "f"(v)); return u;
}
__device__ __forceinline__ float bf16f(unsigned short u) {
    return __uint_as_float((uint32_t)u << 16);
}
__device__ __forceinline__ void split_pack(float v0, float v1,
                                           uint32_t& hi, uint32_t& lo) {
    unsigned short h0 = bf16h(v0), h1 = bf16h(v1);
    unsigned short l0 = bf16h(v0 - bf16f(h0)), l1 = bf16h(v1 - bf16f(h1));
    hi = (uint32_t)h0 | ((uint32_t)h1 << 16);
    lo = (uint32_t)l0 | ((uint32_t)l1 << 16);
}

__device__ __forceinline__ void mma16(float* d, const uint32_t* a, const uint32_t* b) {
    asm("mma.sync.aligned.m16n8k16.row.col.f32.bf16.bf16.f32 "
        "{%0,%1,%2,%3},{%4,%5,%6,%7},{%8,%9},{%0,%1,%2,%3};"
        : "+f"(d[0]), "+f"(d[1]), "+f"(d[2]), "+f"(d[3])
        : "r"(a[0]), "r"(a[1]), "r"(a[2]), "r"(a[3]), "r"(b[0]), "r"(b[1]));
}
__device__ __forceinline__ void mma3x(float* d, const uint32_t* ah, const uint32_t* al,
                                      const uint32_t* bh, const uint32_t* bl) {
    mma16(d, ah, bh);
    mma16(d, ah, bl);
    mma16(d, al, bh);
}
// warp-collective ldmatrix.x4 A-fragment load (addr = per-lane shared addr)
__device__ __forceinline__ void ldsm_a(uint32_t addr, uint32_t* a) {
    asm volatile("ldmatrix.sync.aligned.m8n8.x4.shared.b16 {%0,%1,%2,%3}, [%4];"
                 : "=r"(a[0]), "=r"(a[1]), "=r"(a[2]), "=r"(a[3]) : "r"(addr));
}

__global__ void prep_weights_kernel(
    const float* __restrict__ coef,
    const float* __restrict__ w0, const float* __restrict__ b0,
    const float* __restrict__ ws0, const float* __restrict__ bs0,
    const float* __restrict__ w1, const float* __restrict__ ws1,
    const float* __restrict__ w2, const float* __restrict__ ws2)
{
    int idx = blockIdx.x * blockDim.x + threadIdx.x;
    const int S0 = 8 * 96 * 192;
    const int S1 = 8 * 192;
    const int S2 = 8 * 64 * 256;
    const int S3 = 8 * 32 * 128;
    if (idx < S0) {
        int b = idx / (96 * 192), r = idx % (96 * 192);
        int k2 = r / 192, o = r % 192;
        float v0 = ws0[o * 192 + 2 * k2];
        float v1 = ws0[o * 192 + 2 * k2 + 1];
        #pragma unroll
        for (int e = 0; e < 8; e++) {
            float ce = coef[b * 8 + e];
            v0 = fmaf(ce, w0[e * 36864 + o * 192 + 2 * k2],     v0);
            v1 = fmaf(ce, w0[e * 36864 + o * 192 + 2 * k2 + 1], v1);
        }
        uint32_t hi, lo; split_pack(v0, v1, hi, lo);
        g_W0h[b * 96 * 192 + k2 * 192 + o] = hi;
        g_W0l[b * 96 * 192 + k2 * 192 + o] = lo;
        return;
    }
    idx -= S0;
    if (idx < S1) {
        int b = idx / 192, o = idx % 192;
        float v = bs0[o];
        #pragma unroll
        for (int e = 0; e < 8; e++)
            v = fmaf(coef[b * 8 + e], b0[e * 192 + o], v);
        g_bc0[b * 192 + o] = v;
        return;
    }
    idx -= S1;
    if (idx < S2) {
        int b = idx / (64 * 256), r = idx % (64 * 256);
        int k2 = r / 256, o = r % 256;
        float v0 = ws1[o * 128 + 2 * k2];
        float v1 = ws1[o * 128 + 2 * k2 + 1];
        #pragma unroll
        for (int e = 0; e < 8; e++) {
            float ce = coef[b * 8 + e];
            v0 = fmaf(ce, w1[e * 32768 + o * 128 + 2 * k2],     v0);
            v1 = fmaf(ce, w1[e * 32768 + o * 128 + 2 * k2 + 1], v1);
        }
        uint32_t hi, lo; split_pack(v0, v1, hi, lo);
        g_W1h[b * 64 * 256 + k2 * 256 + o] = hi;
        g_W1l[b * 64 * 256 + k2 * 256 + o] = lo;
        return;
    }
    idx -= S2;
    if (idx < S3) {
        int b = idx / (32 * 128), r = idx % (32 * 128);
        int k2 = r / 128, o = r % 128;
        float v0 = ws2[o * 64 + 2 * k2];
        float v1 = ws2[o * 64 + 2 * k2 + 1];
        #pragma unroll
        for (int e = 0; e < 8; e++) {
            float ce = coef[b * 8 + e];
            v0 = fmaf(ce, w2[e * 8192 + o * 64 + 2 * k2],     v0);
            v1 = fmaf(ce, w2[e * 8192 + o * 64 + 2 * k2 + 1], v1);
        }
        uint32_t hi, lo; split_pack(v0, v1, hi, lo);
        g_W2h[b * 32 * 128 + k2 * 128 + o] = hi;
        g_W2l[b * 32 * 128 + k2 * 128 + o] = lo;
    }
}

__device__ __forceinline__ void mm3(const float* P, const float* Q, float* R) {
    #pragma unroll
    for (int i = 0; i < 3; i++)
        #pragma unroll
        for (int j = 0; j < 3; j++) {
            float acc = 0.f;
            #pragma unroll
            for (int k = 0; k < 3; k++) acc = fmaf(P[i * 3 + k], Q[k * 3 + j], acc);
            R[i * 3 + j] = acc;
        }
}
__device__ __forceinline__ void mm5(const float* P, const float* Q, float* R) {
    #pragma unroll
    for (int i = 0; i < 5; i++)
        #pragma unroll
        for (int j = 0; j < 5; j++) {
            float acc = 0.f;
            #pragma unroll
            for (int k = 0; k < 5; k++) acc = fmaf(P[i * 5 + k], Q[k * 5 + j], acc);
            R[i * 5 + j] = acc;
        }
}

__device__ void build_D(float a1, float a2, float a3,
                        const float* __restrict__ J1g,
                        const float* __restrict__ J2g,
                        float* __restrict__ D1, float* __restrict__ D2)
{
    float J1[9], J2[25];
    #pragma unroll
    for (int i = 0; i < 9; i++) J1[i] = J1g[i];
    #pragma unroll
    for (int i = 0; i < 25; i++) J2[i] = J2g[i];

    float X[3][9], Y[3][25];
    float aa[3] = {a1, a2, a3};
    #pragma unroll
    for (int t = 0; t < 3; t++) {
        float c1, s1, c2, s2;
        sincosf(aa[t], &s1, &c1);
        sincosf(2.0f * aa[t], &s2, &c2);
        float* Xp = X[t];
        Xp[0] = c1;  Xp[1] = 0.f; Xp[2] = s1;
        Xp[3] = 0.f; Xp[4] = 1.f; Xp[5] = 0.f;
        Xp[6] = -s1; Xp[7] = 0.f; Xp[8] = c1;
        float* Yp = Y[t];
        #pragma unroll
        for (int q = 0; q < 25; q++) Yp[q] = 0.f;
        Yp[0]  = c2;  Yp[4]  = s2;
        Yp[6]  = c1;  Yp[8]  = s1;
        Yp[12] = 1.f;
        Yp[16] = -s1; Yp[18] = c1;
        Yp[20] = -s2; Yp[24] = c2;
    }
    float T1[9], T2[9];
    mm3(X[0], J1, T1);
    mm3(T1, X[1], T2);
    mm3(T2, J1, T1);
    mm3(T1, X[2], D1);
    float U1[25], U2[25];
    mm5(Y[0], J2, U1);
    mm5(U1, Y[1], U2);
    mm5(U2, J2, U1);
    mm5(U1, Y[2], D2);
}

// Kernel 1 SMEM (uint32 words):
//   AH [64*292], AL [64*292]  packed bf16x2 planes, [sample][k2], stride 292
//   ST [16*577] fp32 staging; D1f [64*9], D2f [64*25] fp32
#define ASTR2   292
#define SM_AH   0
#define SM_AL   (64 * ASTR2)
#define SM_ST   (2 * 64 * ASTR2)
#define SM_D1F  (SM_ST + 16 * 577)
#define SM_D2F  (SM_D1F + 64 * 9)
#define SM1_TOT (SM_D2F + 64 * 25)

__device__ __forceinline__ void load_b_frag(const uint32_t* __restrict__ W,
                                            int ldo, int k2_0, int o0,
                                            int g, int t, uint32_t* b)
{
    const uint32_t* p = W + (k2_0 + t) * ldo + o0 + g;
    b[0] = p[0];
    b[1] = p[4 * ldo];
}

__global__ __launch_bounds__(NTHR, 1)
void so2_gemm_kernel(const float* __restrict__ x,
                     const float* __restrict__ alpha,
                     const float* __restrict__ beta,
                     const float* __restrict__ gamma_,
                     const float* __restrict__ Jd1,
                     const float* __restrict__ Jd2)
{
    extern __shared__ uint32_t smw[];
    uint32_t* AH = smw + SM_AH;
    uint32_t* AL = smw + SM_AL;
    float* ST  = (float*)(smw + SM_ST);
    float* D1f = (float*)(smw + SM_D1F);
    float* D2f = (float*)(smw + SM_D2F);

    const int tid  = threadIdx.x;
    const int w    = tid >> 5;
    const int lane = tid & 31;
    const int g    = lane >> 2;
    const int t    = lane & 3;
    const int n0   = blockIdx.x * TILE;
    const int b    = n0 / SPB;
    const float* xg = x + (size_t)n0 * 576;

    // ---- Phase 1: fwd Wigner (threads 0-63) + stage pass 0 ----
    if (tid < 64) {
        int n = n0 + tid;
        build_D(alpha[n], beta[n], gamma_[n], Jd1, Jd2,
                D1f + tid * 9, D2f + tid * 25);
    } else {
        for (int idx = tid - 64; idx < 16 * 576; idx += NTHR - 64) {
            int s = idx / 576, d = idx % 576;
            ST[s * 577 + d] = xg[idx];
        }
    }
    __syncthreads();

    // ---- 4 passes: rotate 16 samples, each thread = one channel-PAIR ----
    for (int p = 0; p < 4; p++) {
        {
            int s16 = tid & 15;
            int grp = tid >> 4;
            int s   = p * 16 + s16;
            const float* br = ST + s16 * 577;
            uint32_t* AHs = AH + s * ASTR2;
            uint32_t* ALs = AL + s * ASTR2;
            float d1[9], d2[25];
            #pragma unroll
            for (int j = 0; j < 9; j++)  d1[j] = D1f[s * 9 + j];
            #pragma unroll
            for (int j = 0; j < 25; j++) d2[j] = D2f[s * 25 + j];

            {
                uint32_t hi, lo;
                split_pack(br[2 * grp], br[2 * grp + 1], hi, lo);
                AHs[grp] = hi; ALs[grp] = lo;
            }
            float y0[2], y1[2], y2[2], rr[5][2];
            #pragma unroll
            for (int cc = 0; cc < 2; cc++) {
                int c = 2 * grp + cc;
                float v0 = br[64 + 3 * c], v1 = br[64 + 3 * c + 1], v2 = br[64 + 3 * c + 2];
                y0[cc] = fmaf(d1[0], v0, fmaf(d1[1], v1, d1[2] * v2));
                y1[cc] = fmaf(d1[3], v0, fmaf(d1[4], v1, d1[5] * v2));
                y2[cc] = fmaf(d1[6], v0, fmaf(d1[7], v1, d1[8] * v2));
                float u0 = br[256 + 5 * c],     u1 = br[256 + 5 * c + 1], u2 = br[256 + 5 * c + 2];
                float u3 = br[256 + 5 * c + 3], u4 = br[256 + 5 * c + 4];
                #pragma unroll
                for (int i = 0; i < 5; i++)
                    rr[i][cc] = fmaf(d2[i*5+0], u0, fmaf(d2[i*5+1], u1, fmaf(d2[i*5+2], u2,
                                fmaf(d2[i*5+3], u3, d2[i*5+4] * u4))));
            }
            uint32_t hi, lo;
            split_pack(y0[0], y0[1], hi, lo); AHs[96 + grp]  = hi; ALs[96 + grp]  = lo;
            split_pack(y1[0], y1[1], hi, lo); AHs[32 + grp]  = hi; ALs[32 + grp]  = lo;
            split_pack(y2[0], y2[1], hi, lo); AHs[160 + grp] = hi; ALs[160 + grp] = lo;
            split_pack(rr[0][0], rr[0][1], hi, lo); AHs[224 + grp] = hi; ALs[224 + grp] = lo;
            split_pack(rr[1][0], rr[1][1], hi, lo); AHs[128 + grp] = hi; ALs[128 + grp] = lo;
            split_pack(rr[2][0], rr[2][1], hi, lo); AHs[64 + grp]  = hi; ALs[64 + grp]  = lo;
            split_pack(rr[3][0], rr[3][1], hi, lo); AHs[192 + grp] = hi; ALs[192 + grp] = lo;
            split_pack(rr[4][0], rr[4][1], hi, lo); AHs[256 + grp] = hi; ALs[256 + grp] = lo;
        }
        __syncthreads();
        if (p < 3) {
            const float* xp = xg + (p + 1) * 16 * 576;
            for (int idx = tid; idx < 16 * 576; idx += NTHR) {
                int s = idx / 576, d = idx % 576;
                ST[s * 577 + d] = xp[idx];
            }
            __syncthreads();
        }
    }

    // ldmatrix per-lane base offsets (bytes): row = lane&15, khalf = lane>>4
    const uint32_t lmoff = ((lane & 15) * ASTR2 + (lane >> 4) * 4) * 4;
    const uint32_t ah_base = (uint32_t)__cvta_generic_to_shared(AH) + lmoff;
    const uint32_t al_base = (uint32_t)__cvta_generic_to_shared(AL) + lmoff;

    // ---- Phase 2: 3xBF16 tensor-core GEMMs (m16n8k16, LDSM A frags) ----
    if (w < 8) {
        const uint32_t* Wh = g_W1h + b * 64 * 256;
        const uint32_t* Wl = g_W1l + b * 64 * 256;
        int orb = 16 * w;
        int on[4] = { orb, orb + 8, 128 + orb, 136 + orb };
        #pragma unroll 1
        for (int tt = 0; tt < 2; tt++) {
            float acc[2][2][4][4];
            #pragma unroll
            for (int jj = 0; jj < 2; jj++)
                #pragma unroll
                for (int pp = 0; pp < 2; pp++)
                    #pragma unroll
                    for (int nn = 0; nn < 4; nn++)
                        #pragma unroll
                        for (int c = 0; c < 4; c++) acc[jj][pp][nn][c] = 0.f;
            #pragma unroll 1
            for (int k2_0 = 0; k2_0 < 64; k2_0 += 8) {
                uint32_t Bh[4][2], Bl[4][2];
                #pragma unroll
                for (int nn = 0; nn < 4; nn++) {
                    load_b_frag(Wh, 256, k2_0, on[nn], g, t, Bh[nn]);
                    load_b_frag(Wl, 256, k2_0, on[nn], g, t, Bl[nn]);
                }
                #pragma unroll
                for (int jj = 0; jj < 2; jj++) {
                    int mrow0 = 16 * (2 * tt + jj);
                    #pragma unroll
                    for (int pp = 0; pp < 2; pp++) {
                        uint32_t off = (uint32_t)(mrow0 * ASTR2 + (pp ? 160 : 96) + k2_0) * 4;
                        uint32_t Ah[4], Al[4];
                        ldsm_a(ah_base + off, Ah);
                        ldsm_a(al_base + off, Al);
                        #pragma unroll
                        for (int nn = 0; nn < 4; nn++)
                            mma3x(acc[jj][pp][nn], Ah, Al, Bh[nn], Bl[nn]);
                    }
                }
            }
            #pragma unroll
            for (int jj = 0; jj < 2; jj++) {
                int sbase = 16 * (2 * tt + jj);
                #pragma unroll
                for (int nr = 0; nr < 2; nr++) {
                    #pragma unroll
                    for (int c = 0; c < 4; c++) {
                        int k = orb + 8 * nr + 2 * t + (c & 1);
                        int s = sbase + g + ((c >> 1) ? 8 : 0);
                        float om = acc[jj][0][nr][c]     - acc[jj][1][2 + nr][c];
                        float op = acc[jj][1][nr][c]     + acc[jj][0][2 + nr][c];
                        int dm = (k < 64) ? (64 + 3 * k) : (256 + 5 * (k - 64) + 1);
                        g_tmp[(size_t)dm * NSAMP + n0 + s]       = om;
                        g_tmp[(size_t)(dm + 2) * NSAMP + n0 + s] = op;
                    }
                }
            }
        }
    } else if (w < 12) {
        const uint32_t* Wh = g_W0h + b * 96 * 192;
        const uint32_t* Wl = g_W0l + b * 96 * 192;
        int ow = 48 * (w - 8);
        #pragma unroll 1
        for (int pass = 0; pass < 2; pass++) {
            int o_base = ow + 24 * pass;
            float acc[3][4][4];
            #pragma unroll
            for (int nn = 0; nn < 3; nn++) {
                float bv0 = g_bc0[b * 192 + o_base + 8 * nn + 2 * t];
                float bv1 = g_bc0[b * 192 + o_base + 8 * nn + 2 * t + 1];
                #pragma unroll
                for (int m = 0; m < 4; m++) {
                    acc[nn][m][0] = bv0; acc[nn][m][1] = bv1;
                    acc[nn][m][2] = bv0; acc[nn][m][3] = bv1;
                }
            }
            #pragma unroll 1
            for (int k2_0 = 0; k2_0 < 96; k2_0 += 8) {
                uint32_t Bh[3][2], Bl[3][2];
                #pragma unroll
                for (int nn = 0; nn < 3; nn++) {
                    load_b_frag(Wh, 192, k2_0, o_base + 8 * nn, g, t, Bh[nn]);
                    load_b_frag(Wl, 192, k2_0, o_base + 8 * nn, g, t, Bl[nn]);
                }
                #pragma unroll
                for (int m = 0; m < 4; m++) {
                    uint32_t off = (uint32_t)(16 * m * ASTR2 + k2_0) * 4;
                    uint32_t Ah[4], Al[4];
                    ldsm_a(ah_base + off, Ah);
                    ldsm_a(al_base + off, Al);
                    #pragma unroll
                    for (int nn = 0; nn < 3; nn++)
                        mma3x(acc[nn][m], Ah, Al, Bh[nn], Bl[nn]);
                }
            }
            #pragma unroll
            for (int nn = 0; nn < 3; nn++)
                #pragma unroll
                for (int m = 0; m < 4; m++)
                    #pragma unroll
                    for (int c = 0; c < 4; c++) {
                        int o = o_base + 8 * nn + 2 * t + (c & 1);
                        int s = 16 * m + g + ((c >> 1) ? 8 : 0);
                        int dim = (o < 64) ? o : (o < 128) ? (3 * o - 127) : (5 * o - 382);
                        g_tmp[(size_t)dim * NSAMP + n0 + s] = acc[nn][m][c];
                    }
        }
    } else {
        const uint32_t* Wh = g_W2h + b * 32 * 128;
        const uint32_t* Wl = g_W2l + b * 32 * 128;
        int orb = 16 * (w - 12);
        int on[4] = { orb, orb + 8, 64 + orb, 72 + orb };
        #pragma unroll 1
        for (int tt = 0; tt < 2; tt++) {
            float acc[2][2][4][4];
            #pragma unroll
            for (int jj = 0; jj < 2; jj++)
                #pragma unroll
                for (int pp = 0; pp < 2; pp++)
                    #pragma unroll
                    for (int nn = 0; nn < 4; nn++)
                        #pragma unroll
                        for (int c = 0; c < 4; c++) acc[jj][pp][nn][c] = 0.f;
            #pragma unroll 1
            for (int k2_0 = 0; k2_0 < 32; k2_0 += 8) {
                uint32_t Bh[4][2], Bl[4][2];
                #pragma unroll
                for (int nn = 0; nn < 4; nn++) {
                    load_b_frag(Wh, 128, k2_0, on[nn], g, t, Bh[nn]);
                    load_b_frag(Wl, 128, k2_0, on[nn], g, t, Bl[nn]);
                }
                #pragma unroll
                for (int jj = 0; jj < 2; jj++) {
                    int mrow0 = 16 * (2 * tt + jj);
                    #pragma unroll
                    for (int pp = 0; pp < 2; pp++) {
                        uint32_t off = (uint32_t)(mrow0 * ASTR2 + (pp ? 256 : 224) + k2_0) * 4;
                        uint32_t Ah[4], Al[4];
                        ldsm_a(ah_base + off, Ah);
                        ldsm_a(al_base + off, Al);
                        #pragma unroll
                        for (int nn = 0; nn < 4; nn++)
                            mma3x(acc[jj][pp][nn], Ah, Al, Bh[nn], Bl[nn]);
                    }
                }
            }
            #pragma unroll
            for (int jj = 0; jj < 2; jj++) {
                int sbase = 16 * (2 * tt + jj);
                #pragma unroll
                for (int nr = 0; nr < 2; nr++) {
                    #pragma unroll
                    for (int c = 0; c < 4; c++) {
                        int k = orb + 8 * nr + 2 * t + (c & 1);
                        int s = sbase + g + ((c >> 1) ? 8 : 0);
                        float om = acc[jj][0][nr][c]     - acc[jj][1][2 + nr][c];
                        float op = acc[jj][1][nr][c]     + acc[jj][0][2 + nr][c];
                        int dm = 256 + 5 * k;
                        g_tmp[(size_t)dm * NSAMP + n0 + s]       = om;
                        g_tmp[(size_t)(dm + 4) * NSAMP + n0 + s] = op;
                    }
                }
            }
        }
    }
}

// Kernel 2: back-rotation (unchanged).
#define K2THR 256
#define SM2_S   0
#define SM2_D1B (576 * 33)
#define SM2_D2B (SM2_D1B + 32 * 9)
#define SM2_TOT (SM2_D2B + 32 * 25)

__global__ __launch_bounds__(K2THR, 1)
void so2_backrot_kernel(const float* __restrict__ alpha,
                        const float* __restrict__ beta,
                        const float* __restrict__ gamma_,
                        const float* __restrict__ Jd1,
                        const float* __restrict__ Jd2,
                        float* __restrict__ out)
{
    extern __shared__ float sm[];
    float* S   = sm + SM2_S;
    float* D1b = sm + SM2_D1B;
    float* D2b = sm + SM2_D2B;

    const int tid  = threadIdx.x;
    const int w    = tid >> 5;
    const int lane = tid & 31;
    const int n0   = blockIdx.x * 32;

    for (int idx = tid; idx < 576 * 32; idx += K2THR) {
        int d = idx >> 5, s = idx & 31;
        S[d * 33 + s] = g_tmp[(size_t)d * NSAMP + n0 + s];
    }
    if (tid < 32) {
        int n = n0 + tid;
        build_D(-gamma_[n], -beta[n], -alpha[n], Jd1, Jd2,
                D1b + tid * 9, D2b + tid * 25);
    }
    __syncthreads();

    {
        float e1[9], e2[25];
        #pragma unroll
        for (int j = 0; j < 9; j++)  e1[j] = D1b[lane * 9 + j];
        #pragma unroll
        for (int j = 0; j < 25; j++) e2[j] = D2b[lane * 25 + j];
        #pragma unroll
        for (int k = 0; k < 8; k++) {
            int c = w + 8 * k;
            float v0 = S[(64 + 3 * c) * 33 + lane];
            float v1 = S[(64 + 3 * c + 1) * 33 + lane];
            float v2 = S[(64 + 3 * c + 2) * 33 + lane];
            S[(64 + 3 * c) * 33 + lane]     = fmaf(e1[0], v0, fmaf(e1[1], v1, e1[2] * v2));
            S[(64 + 3 * c + 1) * 33 + lane] = fmaf(e1[3], v0, fmaf(e1[4], v1, e1[5] * v2));
            S[(64 + 3 * c + 2) * 33 + lane] = fmaf(e1[6], v0, fmaf(e1[7], v1, e1[8] * v2));
            float u0 = S[(256 + 5 * c) * 33 + lane];
            float u1 = S[(256 + 5 * c + 1) * 33 + lane];
            float u2 = S[(256 + 5 * c + 2) * 33 + lane];
            float u3 = S[(256 + 5 * c + 3) * 33 + lane];
            float u4 = S[(256 + 5 * c + 4) * 33 + lane];
            #pragma unroll
            for (int i = 0; i < 5; i++)
                S[(256 + 5 * c + i) * 33 + lane] =
                    fmaf(e2[i*5+0], u0, fmaf(e2[i*5+1], u1, fmaf(e2[i*5+2], u2,
                    fmaf(e2[i*5+3], u3, e2[i*5+4] * u4))));
        }
    }
    __syncthreads();

    for (int idx = tid; idx < 32 * 576; idx += K2THR) {
        int s = idx / 576, d = idx % 576;
        out[(size_t)(n0 + s) * 576 + d] = S[d * 33 + s];
    }
}

extern "C" void kernel_launch(void* const* d_in, const int* in_sizes, int n_in,
                              void* d_out, int out_size)
{
    const float* x     = (const float*)d_in[0];
    const float* alpha = (const float*)d_in[1];
    const float* beta  = (const float*)d_in[2];
    const float* gamma_= (const float*)d_in[3];
    const float* coef  = (const float*)d_in[4];
    const float* Jd1   = (const float*)d_in[5];
    const float* Jd2   = (const float*)d_in[6];
    const float* w0    = (const float*)d_in[7];
    const float* b0    = (const float*)d_in[8];
    const float* ws0   = (const float*)d_in[9];
    const float* bs0   = (const float*)d_in[10];
    const float* w1    = (const float*)d_in[11];
    const float* ws1   = (const float*)d_in[12];
    const float* w2    = (const float*)d_in[13];
    const float* ws2   = (const float*)d_in[14];
    float* out = (float*)d_out;

    const int totalW = 8 * 96 * 192 + 8 * 192 + 8 * 64 * 256 + 8 * 32 * 128;
    prep_weights_kernel<<<(totalW + 255) / 256, 256>>>(coef, w0, b0, ws0, bs0,
                                                       w1, ws1, w2, ws2);

    const int smem1 = SM1_TOT * sizeof(uint32_t);
    cudaFuncSetAttribute(so2_gemm_kernel,
                         cudaFuncAttributeMaxDynamicSharedMemorySize, smem1);
    so2_gemm_kernel<<<NSAMP / TILE, NTHR, smem1>>>(x, alpha, beta, gamma_, Jd1, Jd2);

    const int smem2 = SM2_TOT * sizeof(float);
    cudaFuncSetAttribute(so2_backrot_kernel,
                         cudaFuncAttributeMaxDynamicSharedMemorySize, smem2);
    so2_backrot_kernel<<<NSAMP / 32, K2THR, smem2>>>(alpha, beta, gamma_,
                                                     Jd1, Jd2, out);
}

// round 17
// speedup vs baseline: 2.3894x; 1.0132x over previous
#include <cuda_runtime.h>
#include <math.h>
#include <stdint.h>

#define NSAMP 64000
#define TILE  64
#define NTHR  512
#define SPB   8000

// Fragment-major ("quad") weight layout: per (b, k16-step ks, o-tile ot) a
// 32-uint4 tile; lane l = (o&7)*4 + (k2&3); uint4 = {b0h, b1h, b0l, b1l}
// where b0 = k2 row ks*8+t, b1 = row ks*8+t+4.
__device__ __align__(16) uint4 g_W0q[8 * 9216];  // K2=96 (12 ks) x 24 ot x 32
__device__ __align__(16) uint4 g_W1q[8 * 8192];  // K2=64 (8 ks)  x 32 ot x 32
__device__ __align__(16) uint4 g_W2q[8 * 2048];  // K2=32 (4 ks)  x 16 ot x 32
__device__ __align__(16) float g_bc0[8 * 192];
__device__ float g_tmp[576 * NSAMP];

__device__ __forceinline__ unsigned short bf16h(float v) {
    unsigned short u; asm("cvt.rn.bf16.f32 %0, %1;" : "=h"(u) : "f"(v)); return u;
}
__device__ __forceinline__ float bf16f(unsigned short u) {
    return __uint_as_float((uint32_t)u << 16);
}
__device__ __forceinline__ void split_pack(float v0, float v1,
                                           uint32_t& hi, uint32_t& lo) {
    unsigned short h0 = bf16h(v0), h1 = bf16h(v1);
    unsigned short l0 = bf16h(v0 - bf16f(h0)), l1 = bf16h(v1 - bf16f(h1));
    hi = (uint32_t)h0 | ((uint32_t)h1 << 16);
    lo = (uint32_t)l0 | ((uint32_t)l1 << 16);
}

__device__ __forceinline__ void mma16(float* d, const uint32_t* a, const uint32_t* b) {
    asm("mma.sync.aligned.m16n8k16.row.col.f32.bf16.bf16.f32 "
        "{%0,%1,%2,%3},{%4,%5,%6,%7},{%8,%9},{%0,%1,%2,%3};"
        : "+f"(d[0]), "+f"(d[1]), "+f"(d[2]), "+f"(d[3])
        : "r"(a[0]), "r"(a[1]), "r"(a[2]), "r"(a[3]), "r"(b[0]), "r"(b[1]));
}
__device__ __forceinline__ void mma3x(float* d, const uint32_t* ah, const uint32_t* al,
                                      const uint32_t* bh, const uint32_t* bl) {
    mma16(d, ah, bh);
    mma16(d, ah, bl);
    mma16(d, al, bh);
}
__device__ __forceinline__ void ldsm_a(uint32_t addr, uint32_t* a) {
    asm volatile("ldmatrix.sync.aligned.m8n8.x4.shared.b16 {%0,%1,%2,%3}, [%4];"
                 : "=r"(a[0]), "=r"(a[1]), "=r"(a[2]), "=r"(a[3]) : "r"(addr));
}

// prep: one thread per (b, k2, o); writes hi/lo words into quad layout.
__global__ void prep_weights_kernel(
    const float* __restrict__ coef,
    const float* __restrict__ w0, const float* __restrict__ b0,
    const float* __restrict__ ws0, const float* __restrict__ bs0,
    const float* __restrict__ w1, const float* __restrict__ ws1,
    const float* __restrict__ w2, const float* __restrict__ ws2)
{
    int idx = blockIdx.x * blockDim.x + threadIdx.x;
    const int S0 = 8 * 96 * 192;
    const int S1 = 8 * 192;
    const int S2 = 8 * 64 * 256;
    const int S3 = 8 * 32 * 128;
    if (idx < S0) {
        int b = idx / (96 * 192), r = idx % (96 * 192);
        int k2 = r / 192, o = r % 192;
        float v0 = ws0[o * 192 + 2 * k2];
        float v1 = ws0[o * 192 + 2 * k2 + 1];
        #pragma unroll
        for (int e = 0; e < 8; e++) {
            float ce = coef[b * 8 + e];
            v0 = fmaf(ce, w0[e * 36864 + o * 192 + 2 * k2],     v0);
            v1 = fmaf(ce, w0[e * 36864 + o * 192 + 2 * k2 + 1], v1);
        }
        uint32_t hi, lo; split_pack(v0, v1, hi, lo);
        int ks = k2 >> 3, rr = k2 & 7, h = rr >> 2, tt = rr & 3;
        int lane = (o & 7) * 4 + tt;
        size_t slot = (size_t)b * 9216 + (ks * 24 + (o >> 3)) * 32 + lane;
        uint32_t* wq = (uint32_t*)g_W0q;
        wq[slot * 4 + h]     = hi;
        wq[slot * 4 + 2 + h] = lo;
        return;
    }
    idx -= S0;
    if (idx < S1) {
        int b = idx / 192, o = idx % 192;
        float v = bs0[o];
        #pragma unroll
        for (int e = 0; e < 8; e++)
            v = fmaf(coef[b * 8 + e], b0[e * 192 + o], v);
        g_bc0[b * 192 + o] = v;
        return;
    }
    idx -= S1;
    if (idx < S2) {
        int b = idx / (64 * 256), r = idx % (64 * 256);
        int k2 = r / 256, o = r % 256;
        float v0 = ws1[o * 128 + 2 * k2];
        float v1 = ws1[o * 128 + 2 * k2 + 1];
        #pragma unroll
        for (int e = 0; e < 8; e++) {
            float ce = coef[b * 8 + e];
            v0 = fmaf(ce, w1[e * 32768 + o * 128 + 2 * k2],     v0);
            v1 = fmaf(ce, w1[e * 32768 + o * 128 + 2 * k2 + 1], v1);
        }
        uint32_t hi, lo; split_pack(v0, v1, hi, lo);
        int ks = k2 >> 3, rr = k2 & 7, h = rr >> 2, tt = rr & 3;
        int lane = (o & 7) * 4 + tt;
        size_t slot = (size_t)b * 8192 + (ks * 32 + (o >> 3)) * 32 + lane;
        uint32_t* wq = (uint32_t*)g_W1q;
        wq[slot * 4 + h]     = hi;
        wq[slot * 4 + 2 + h] = lo;
        return;
    }
    idx -= S2;
    if (idx < S3) {
        int b = idx / (32 * 128), r = idx % (32 * 128);
        int k2 = r / 128, o = r % 128;
        float v0 = ws2[o * 64 + 2 * k2];
        float v1 = ws2[o * 64 + 2 * k2 + 1];
        #pragma unroll
        for (int e = 0; e < 8; e++) {
            float ce = coef[b * 8 + e];
            v0 = fmaf(ce, w2[e * 8192 + o * 64 + 2 * k2],     v0);
            v1 = fmaf(ce, w2[e * 8192 + o * 64 + 2 * k2 + 1], v1);
        }
        uint32_t hi, lo; split_pack(v0, v1, hi, lo);
        int ks = k2 >> 3, rr = k2 & 7, h = rr >> 2, tt = rr & 3;
        int lane = (o & 7) * 4 + tt;
        size_t slot = (size_t)b * 2048 + (ks * 16 + (o >> 3)) * 32 + lane;
        uint32_t* wq = (uint32_t*)g_W2q;
        wq[slot * 4 + h]     = hi;
        wq[slot * 4 + 2 + h] = lo;
    }
}

__device__ __forceinline__ void mm3(const float* P, const float* Q, float* R) {
    #pragma unroll
    for (int i = 0; i < 3; i++)
        #pragma unroll
        for (int j = 0; j < 3; j++) {
            float acc = 0.f;
            #pragma unroll
            for (int k = 0; k < 3; k++) acc = fmaf(P[i * 3 + k], Q[k * 3 + j], acc);
            R[i * 3 + j] = acc;
        }
}
__device__ __forceinline__ void mm5(const float* P, const float* Q, float* R) {
    #pragma unroll
    for (int i = 0; i < 5; i++)
        #pragma unroll
        for (int j = 0; j < 5; j++) {
            float acc = 0.f;
            #pragma unroll
            for (int k = 0; k < 5; k++) acc = fmaf(P[i * 5 + k], Q[k * 5 + j], acc);
            R[i * 5 + j] = acc;
        }
}

__device__ void build_D(float a1, float a2, float a3,
                        const float* __restrict__ J1g,
                        const float* __restrict__ J2g,
                        float* __restrict__ D1, float* __restrict__ D2)
{
    float J1[9], J2[25];
    #pragma unroll
    for (int i = 0; i < 9; i++) J1[i] = J1g[i];
    #pragma unroll
    for (int i = 0; i < 25; i++) J2[i] = J2g[i];

    float X[3][9], Y[3][25];
    float aa[3] = {a1, a2, a3};
    #pragma unroll
    for (int t = 0; t < 3; t++) {
        float c1, s1, c2, s2;
        sincosf(aa[t], &s1, &c1);
        sincosf(2.0f * aa[t], &s2, &c2);
        float* Xp = X[t];
        Xp[0] = c1;  Xp[1] = 0.f; Xp[2] = s1;
        Xp[3] = 0.f; Xp[4] = 1.f; Xp[5] = 0.f;
        Xp[6] = -s1; Xp[7] = 0.f; Xp[8] = c1;
        float* Yp = Y[t];
        #pragma unroll
        for (int q = 0; q < 25; q++) Yp[q] = 0.f;
        Yp[0]  = c2;  Yp[4]  = s2;
        Yp[6]  = c1;  Yp[8]  = s1;
        Yp[12] = 1.f;
        Yp[16] = -s1; Yp[18] = c1;
        Yp[20] = -s2; Yp[24] = c2;
    }
    float T1[9], T2[9];
    mm3(X[0], J1, T1);
    mm3(T1, X[1], T2);
    mm3(T2, J1, T1);
    mm3(T1, X[2], D1);
    float U1[25], U2[25];
    mm5(Y[0], J2, U1);
    mm5(U1, Y[1], U2);
    mm5(U2, J2, U1);
    mm5(U1, Y[2], D2);
}

// Kernel 1 SMEM (uint32 words):
//   AH [64*292], AL [64*292]  packed bf16x2 planes, [sample][k2], stride 292
//   ST [16*577] fp32 staging; D1f [64*9], D2f [64*25] fp32
#define ASTR2   292
#define SM_AH   0
#define SM_AL   (64 * ASTR2)
#define SM_ST   (2 * 64 * ASTR2)
#define SM_D1F  (SM_ST + 16 * 577)
#define SM_D2F  (SM_D1F + 64 * 9)
#define SM1_TOT (SM_D2F + 64 * 25)

__global__ __launch_bounds__(NTHR, 1)
void so2_gemm_kernel(const float* __restrict__ x,
                     const float* __restrict__ alpha,
                     const float* __restrict__ beta,
                     const float* __restrict__ gamma_,
                     const float* __restrict__ Jd1,
                     const float* __restrict__ Jd2)
{
    extern __shared__ uint32_t smw[];
    uint32_t* AH = smw + SM_AH;
    uint32_t* AL = smw + SM_AL;
    float* ST  = (float*)(smw + SM_ST);
    float* D1f = (float*)(smw + SM_D1F);
    float* D2f = (float*)(smw + SM_D2F);

    const int tid  = threadIdx.x;
    const int w    = tid >> 5;
    const int lane = tid & 31;
    const int g    = lane >> 2;
    const int t    = lane & 3;
    const int n0   = blockIdx.x * TILE;
    const int b    = n0 / SPB;
    const float* xg = x + (size_t)n0 * 576;

    // ---- Phase 1: fwd Wigner (threads 0-63) + stage pass 0 ----
    if (tid < 64) {
        int n = n0 + tid;
        build_D(alpha[n], beta[n], gamma_[n], Jd1, Jd2,
                D1f + tid * 9, D2f + tid * 25);
    } else {
        for (int idx = tid - 64; idx < 16 * 576; idx += NTHR - 64) {
            int s = idx / 576, d = idx % 576;
            ST[s * 577 + d] = xg[idx];
        }
    }
    __syncthreads();

    // ---- 4 passes: rotate 16 samples, each thread = one channel-PAIR ----
    for (int p = 0; p < 4; p++) {
        {
            int s16 = tid & 15;
            int grp = tid >> 4;
            int s   = p * 16 + s16;
            const float* br = ST + s16 * 577;
            uint32_t* AHs = AH + s * ASTR2;
            uint32_t* ALs = AL + s * ASTR2;
            float d1[9], d2[25];
            #pragma unroll
            for (int j = 0; j < 9; j++)  d1[j] = D1f[s * 9 + j];
            #pragma unroll
            for (int j = 0; j < 25; j++) d2[j] = D2f[s * 25 + j];

            {
                uint32_t hi, lo;
                split_pack(br[2 * grp], br[2 * grp + 1], hi, lo);
                AHs[grp] = hi; ALs[grp] = lo;
            }
            float y0[2], y1[2], y2[2], rr[5][2];
            #pragma unroll
            for (int cc = 0; cc < 2; cc++) {
                int c = 2 * grp + cc;
                float v0 = br[64 + 3 * c], v1 = br[64 + 3 * c + 1], v2 = br[64 + 3 * c + 2];
                y0[cc] = fmaf(d1[0], v0, fmaf(d1[1], v1, d1[2] * v2));
                y1[cc] = fmaf(d1[3], v0, fmaf(d1[4], v1, d1[5] * v2));
                y2[cc] = fmaf(d1[6], v0, fmaf(d1[7], v1, d1[8] * v2));
                float u0 = br[256 + 5 * c],     u1 = br[256 + 5 * c + 1], u2 = br[256 + 5 * c + 2];
                float u3 = br[256 + 5 * c + 3], u4 = br[256 + 5 * c + 4];
                #pragma unroll
                for (int i = 0; i < 5; i++)
                    rr[i][cc] = fmaf(d2[i*5+0], u0, fmaf(d2[i*5+1], u1, fmaf(d2[i*5+2], u2,
                                fmaf(d2[i*5+3], u3, d2[i*5+4] * u4))));
            }
            uint32_t hi, lo;
            split_pack(y0[0], y0[1], hi, lo); AHs[96 + grp]  = hi; ALs[96 + grp]  = lo;
            split_pack(y1[0], y1[1], hi, lo); AHs[32 + grp]  = hi; ALs[32 + grp]  = lo;
            split_pack(y2[0], y2[1], hi, lo); AHs[160 + grp] = hi; ALs[160 + grp] = lo;
            split_pack(rr[0][0], rr[0][1], hi, lo); AHs[224 + grp] = hi; ALs[224 + grp] = lo;
            split_pack(rr[1][0], rr[1][1], hi, lo); AHs[128 + grp] = hi; ALs[128 + grp] = lo;
            split_pack(rr[2][0], rr[2][1], hi, lo); AHs[64 + grp]  = hi; ALs[64 + grp]  = lo;
            split_pack(rr[3][0], rr[3][1], hi, lo); AHs[192 + grp] = hi; ALs[192 + grp] = lo;
            split_pack(rr[4][0], rr[4][1], hi, lo); AHs[256 + grp] = hi; ALs[256 + grp] = lo;
        }
        __syncthreads();
        if (p < 3) {
            const float* xp = xg + (p + 1) * 16 * 576;
            for (int idx = tid; idx < 16 * 576; idx += NTHR) {
                int s = idx / 576, d = idx % 576;
                ST[s * 577 + d] = xp[idx];
            }
            __syncthreads();
        }
    }

    // ldmatrix per-lane base offsets (bytes)
    const uint32_t lmoff = ((lane & 15) * ASTR2 + (lane >> 4) * 4) * 4;
    const uint32_t ah_base = (uint32_t)__cvta_generic_to_shared(AH) + lmoff;
    const uint32_t al_base = (uint32_t)__cvta_generic_to_shared(AL) + lmoff;

    // ---- Phase 2: 3xBF16 tensor-core GEMMs (LDSM A, quad-coalesced B) ----
    if (w < 8) {
        const uint4* Wq = g_W1q + (size_t)b * 8192;
        int orb = 16 * w;
        int on[4] = { orb, orb + 8, 128 + orb, 136 + orb };
        #pragma unroll 1
        for (int tt = 0; tt < 2; tt++) {
            float acc[2][2][4][4];
            #pragma unroll
            for (int jj = 0; jj < 2; jj++)
                #pragma unroll
                for (int pp = 0; pp < 2; pp++)
                    #pragma unroll
                    for (int nn = 0; nn < 4; nn++)
                        #pragma unroll
                        for (int c = 0; c < 4; c++) acc[jj][pp][nn][c] = 0.f;
            #pragma unroll 1
            for (int k2_0 = 0; k2_0 < 64; k2_0 += 8) {
                uint32_t Bh[4][2], Bl[4][2];
                #pragma unroll
                for (int nn = 0; nn < 4; nn++) {
                    uint4 v = Wq[((size_t)(k2_0 >> 3) * 32 + (on[nn] >> 3)) * 32 + lane];
                    Bh[nn][0] = v.x; Bh[nn][1] = v.y;
                    Bl[nn][0] = v.z; Bl[nn][1] = v.w;
                }
                #pragma unroll
                for (int jj = 0; jj < 2; jj++) {
                    int mrow0 = 16 * (2 * tt + jj);
                    #pragma unroll
                    for (int pp = 0; pp < 2; pp++) {
                        uint32_t off = (uint32_t)(mrow0 * ASTR2 + (pp ? 160 : 96) + k2_0) * 4;
                        uint32_t Ah[4], Al[4];
                        ldsm_a(ah_base + off, Ah);
                        ldsm_a(al_base + off, Al);
                        #pragma unroll
                        for (int nn = 0; nn < 4; nn++)
                            mma3x(acc[jj][pp][nn], Ah, Al, Bh[nn], Bl[nn]);
                    }
                }
            }
            #pragma unroll
            for (int jj = 0; jj < 2; jj++) {
                int sbase = 16 * (2 * tt + jj);
                #pragma unroll
                for (int nr = 0; nr < 2; nr++) {
                    #pragma unroll
                    for (int c = 0; c < 4; c++) {
                        int k = orb + 8 * nr + 2 * t + (c & 1);
                        int s = sbase + g + ((c >> 1) ? 8 : 0);
                        float om = acc[jj][0][nr][c]     - acc[jj][1][2 + nr][c];
                        float op = acc[jj][1][nr][c]     + acc[jj][0][2 + nr][c];
                        int dm = (k < 64) ? (64 + 3 * k) : (256 + 5 * (k - 64) + 1);
                        g_tmp[(size_t)dm * NSAMP + n0 + s]       = om;
                        g_tmp[(size_t)(dm + 2) * NSAMP + n0 + s] = op;
                    }
                }
            }
        }
    } else if (w < 12) {
        const uint4* Wq = g_W0q + (size_t)b * 9216;
        int ow = 48 * (w - 8);
        #pragma unroll 1
        for (int pass = 0; pass < 2; pass++) {
            int o_base = ow + 24 * pass;
            float acc[3][4][4];
            #pragma unroll
            for (int nn = 0; nn < 3; nn++) {
                float bv0 = g_bc0[b * 192 + o_base + 8 * nn + 2 * t];
                float bv1 = g_bc0[b * 192 + o_base + 8 * nn + 2 * t + 1];
                #pragma unroll
                for (int m = 0; m < 4; m++) {
                    acc[nn][m][0] = bv0; acc[nn][m][1] = bv1;
                    acc[nn][m][2] = bv0; acc[nn][m][3] = bv1;
                }
            }
            #pragma unroll 1
            for (int k2_0 = 0; k2_0 < 96; k2_0 += 8) {
                uint32_t Bh[3][2], Bl[3][2];
                #pragma unroll
                for (int nn = 0; nn < 3; nn++) {
                    uint4 v = Wq[((size_t)(k2_0 >> 3) * 24 + ((o_base + 8 * nn) >> 3)) * 32 + lane];
                    Bh[nn][0] = v.x; Bh[nn][1] = v.y;
                    Bl[nn][0] = v.z; Bl[nn][1] = v.w;
                }
                #pragma unroll
                for (int m = 0; m < 4; m++) {
                    uint32_t off = (uint32_t)(16 * m * ASTR2 + k2_0) * 4;
                    uint32_t Ah[4], Al[4];
                    ldsm_a(ah_base + off, Ah);
                    ldsm_a(al_base + off, Al);
                    #pragma unroll
                    for (int nn = 0; nn < 3; nn++)
                        mma3x(acc[nn][m], Ah, Al, Bh[nn], Bl[nn]);
                }
            }
            #pragma unroll
            for (int nn = 0; nn < 3; nn++)
                #pragma unroll
                for (int m = 0; m < 4; m++)
                    #pragma unroll
                    for (int c = 0; c < 4; c++) {
                        int o = o_base + 8 * nn + 2 * t + (c & 1);
                        int s = 16 * m + g + ((c >> 1) ? 8 : 0);
                        int dim = (o < 64) ? o : (o < 128) ? (3 * o - 127) : (5 * o - 382);
                        g_tmp[(size_t)dim * NSAMP + n0 + s] = acc[nn][m][c];
                    }
        }
    } else {
        const uint4* Wq = g_W2q + (size_t)b * 2048;
        int orb = 16 * (w - 12);
        int on[4] = { orb, orb + 8, 64 + orb, 72 + orb };
        #pragma unroll 1
        for (int tt = 0; tt < 2; tt++) {
            float acc[2][2][4][4];
            #pragma unroll
            for (int jj = 0; jj < 2; jj++)
                #pragma unroll
                for (int pp = 0; pp < 2; pp++)
                    #pragma unroll
                    for (int nn = 0; nn < 4; nn++)
                        #pragma unroll
                        for (int c = 0; c < 4; c++) acc[jj][pp][nn][c] = 0.f;
            #pragma unroll 1
            for (int k2_0 = 0; k2_0 < 32; k2_0 += 8) {
                uint32_t Bh[4][2], Bl[4][2];
                #pragma unroll
                for (int nn = 0; nn < 4; nn++) {
                    uint4 v = Wq[((size_t)(k2_0 >> 3) * 16 + (on[nn] >> 3)) * 32 + lane];
                    Bh[nn][0] = v.x; Bh[nn][1] = v.y;
                    Bl[nn][0] = v.z; Bl[nn][1] = v.w;
                }
                #pragma unroll
                for (int jj = 0; jj < 2; jj++) {
                    int mrow0 = 16 * (2 * tt + jj);
                    #pragma unroll
                    for (int pp = 0; pp < 2; pp++) {
                        uint32_t off = (uint32_t)(mrow0 * ASTR2 + (pp ? 256 : 224) + k2_0) * 4;
                        uint32_t Ah[4], Al[4];
                        ldsm_a(ah_base + off, Ah);
                        ldsm_a(al_base + off, Al);
                        #pragma unroll
                        for (int nn = 0; nn < 4; nn++)
                            mma3x(acc[jj][pp][nn], Ah, Al, Bh[nn], Bl[nn]);
                    }
                }
            }
            #pragma unroll
            for (int jj = 0; jj < 2; jj++) {
                int sbase = 16 * (2 * tt + jj);
                #pragma unroll
                for (int nr = 0; nr < 2; nr++) {
                    #pragma unroll
                    for (int c = 0; c < 4; c++) {
                        int k = orb + 8 * nr + 2 * t + (c & 1);
                        int s = sbase + g + ((c >> 1) ? 8 : 0);
                        float om = acc[jj][0][nr][c]     - acc[jj][1][2 + nr][c];
                        float op = acc[jj][1][nr][c]     + acc[jj][0][2 + nr][c];
                        int dm = 256 + 5 * k;
                        g_tmp[(size_t)dm * NSAMP + n0 + s]       = om;
                        g_tmp[(size_t)(dm + 4) * NSAMP + n0 + s] = op;
                    }
                }
            }
        }
    }
}

// Kernel 2: back-rotation (unchanged).
#define K2THR 256
#define SM2_S   0
#define SM2_D1B (576 * 33)
#define SM2_D2B (SM2_D1B + 32 * 9)
#define SM2_TOT (SM2_D2B + 32 * 25)

__global__ __launch_bounds__(K2THR, 1)
void so2_backrot_kernel(const float* __restrict__ alpha,
                        const float* __restrict__ beta,
                        const float* __restrict__ gamma_,
                        const float* __restrict__ Jd1,
                        const float* __restrict__ Jd2,
                        float* __restrict__ out)
{
    extern __shared__ float sm[];
    float* S   = sm + SM2_S;
    float* D1b = sm + SM2_D1B;
    float* D2b = sm + SM2_D2B;

    const int tid  = threadIdx.x;
    const int w    = tid >> 5;
    const int lane = tid & 31;
    const int n0   = blockIdx.x * 32;

    for (int idx = tid; idx < 576 * 32; idx += K2THR) {
        int d = idx >> 5, s = idx & 31;
        S[d * 33 + s] = g_tmp[(size_t)d * NSAMP + n0 + s];
    }
    if (tid < 32) {
        int n = n0 + tid;
        build_D(-gamma_[n], -beta[n], -alpha[n], Jd1, Jd2,
                D1b + tid * 9, D2b + tid * 25);
    }
    __syncthreads();

    {
        float e1[9], e2[25];
        #pragma unroll
        for (int j = 0; j < 9; j++)  e1[j] = D1b[lane * 9 + j];
        #pragma unroll
        for (int j = 0; j < 25; j++) e2[j] = D2b[lane * 25 + j];
        #pragma unroll
        for (int k = 0; k < 8; k++) {
            int c = w + 8 * k;
            float v0 = S[(64 + 3 * c) * 33 + lane];
            float v1 = S[(64 + 3 * c + 1) * 33 + lane];
            float v2 = S[(64 + 3 * c + 2) * 33 + lane];
            S[(64 + 3 * c) * 33 + lane]     = fmaf(e1[0], v0, fmaf(e1[1], v1, e1[2] * v2));
            S[(64 + 3 * c + 1) * 33 + lane] = fmaf(e1[3], v0, fmaf(e1[4], v1, e1[5] * v2));
            S[(64 + 3 * c + 2) * 33 + lane] = fmaf(e1[6], v0, fmaf(e1[7], v1, e1[8] * v2));
            float u0 = S[(256 + 5 * c) * 33 + lane];
            float u1 = S[(256 + 5 * c + 1) * 33 + lane];
            float u2 = S[(256 + 5 * c + 2) * 33 + lane];
            float u3 = S[(256 + 5 * c + 3) * 33 + lane];
            float u4 = S[(256 + 5 * c + 4) * 33 + lane];
            #pragma unroll
            for (int i = 0; i < 5; i++)
                S[(256 + 5 * c + i) * 33 + lane] =
                    fmaf(e2[i*5+0], u0, fmaf(e2[i*5+1], u1, fmaf(e2[i*5+2], u2,
                    fmaf(e2[i*5+3], u3, e2[i*5+4] * u4))));
        }
    }
    __syncthreads();

    for (int idx = tid; idx < 32 * 576; idx += K2THR) {
        int s = idx / 576, d = idx % 576;
        out[(size_t)(n0 + s) * 576 + d] = S[d * 33 + s];
    }
}

extern "C" void kernel_launch(void* const* d_in, const int* in_sizes, int n_in,
                              void* d_out, int out_size)
{
    const float* x     = (const float*)d_in[0];
    const float* alpha = (const float*)d_in[1];
    const float* beta  = (const float*)d_in[2];
    const float* gamma_= (const float*)d_in[3];
    const float* coef  = (const float*)d_in[4];
    const float* Jd1   = (const float*)d_in[5];
    const float* Jd2   = (const float*)d_in[6];
    const float* w0    = (const float*)d_in[7];
    const float* b0    = (const float*)d_in[8];
    const float* ws0   = (const float*)d_in[9];
    const float* bs0   = (const float*)d_in[10];
    const float* w1    = (const float*)d_in[11];
    const float* ws1   = (const float*)d_in[12];
    const float* w2    = (const float*)d_in[13];
    const float* ws2   = (const float*)d_in[14];
    float* out = (float*)d_out;

    const int totalW = 8 * 96 * 192 + 8 * 192 + 8 * 64 * 256 + 8 * 32 * 128;
    prep_weights_kernel<<<(totalW + 255) / 256, 256>>>(coef, w0, b0, ws0, bs0,
                                                       w1, ws1, w2, ws2);

    const int smem1 = SM1_TOT * sizeof(uint32_t);
    cudaFuncSetAttribute(so2_gemm_kernel,
                         cudaFuncAttributeMaxDynamicSharedMemorySize, smem1);
    so2_gemm_kernel<<<NSAMP / TILE, NTHR, smem1>>>(x, alpha, beta, gamma_, Jd1, Jd2);

    const int smem2 = SM2_TOT * sizeof(float);
    cudaFuncSetAttribute(so2_backrot_kernel,
                         cudaFuncAttributeMaxDynamicSharedMemorySize, smem2);
    so2_backrot_kernel<<<NSAMP / 32, K2THR, smem2>>>(alpha, beta, gamma_,
                                                     Jd1, Jd2, out);
}